// round 1
// baseline (speedup 1.0000x reference)
#include <cuda_runtime.h>
#include <math.h>

#define TT 2048
#define BB 64
#define HH 512
#define GG 2048   // 4*HH

// Scratch (module-load allocated, endorsed by harness rules).
// g_xg is reused by both layers (layer-1 XG fully consumed before layer-2 GEMM).
__device__ float g_xg[268435456];              // TT*BB*GG = 1 GB
__device__ float g_h1[134217728 / 2];          // TT*BB*HH = 67,108,864 floats
__device__ float g_h2[134217728 / 2];
__device__ unsigned g_count;                   // zero-init at module load
__device__ volatile unsigned g_gen;

__device__ __forceinline__ float sigm(float x) { return 1.0f / (1.0f + expf(-x)); }

// ---------------------------------------------------------------------------
// GEMM: C[M x 2048] = A[M x K] * B[2048 x K]^T + bi[n] + bh[n]
// Tile 64x64, BK=32, 256 threads, 4x4 per thread. K in {256, 512}.
// ---------------------------------------------------------------------------
__global__ __launch_bounds__(256) void gemm_xg(
    const float* __restrict__ A, const float* __restrict__ B,
    const float* __restrict__ bi, const float* __restrict__ bh,
    float* __restrict__ C, int K)
{
    __shared__ float sA[32 * 68];   // stored transposed [k][m], pad 68
    __shared__ float sB[32 * 68];   // [k][n]

    const int tid = threadIdx.x;
    const int tx = tid & 15;        // n quad
    const int ty = tid >> 4;        // m quad
    const int m0 = blockIdx.y * 64;
    const int n0 = blockIdx.x * 64;
    const int r0 = tid >> 3;        // 0..31
    const int kq = tid & 7;         // 0..7 (k quad)

    float4 acc0 = {0,0,0,0}, acc1 = {0,0,0,0}, acc2 = {0,0,0,0}, acc3 = {0,0,0,0};

    for (int kb = 0; kb < K; kb += 32) {
        #pragma unroll
        for (int half = 0; half < 2; half++) {
            int r = r0 + half * 32;
            float4 av = __ldg((const float4*)&A[(size_t)(m0 + r) * K + kb + kq * 4]);
            float4 bv = __ldg((const float4*)&B[(size_t)(n0 + r) * K + kb + kq * 4]);
            sA[(kq*4+0)*68 + r] = av.x; sA[(kq*4+1)*68 + r] = av.y;
            sA[(kq*4+2)*68 + r] = av.z; sA[(kq*4+3)*68 + r] = av.w;
            sB[(kq*4+0)*68 + r] = bv.x; sB[(kq*4+1)*68 + r] = bv.y;
            sB[(kq*4+2)*68 + r] = bv.z; sB[(kq*4+3)*68 + r] = bv.w;
        }
        __syncthreads();
        const float4* As4 = (const float4*)sA;   // row = 17 quads
        const float4* Bs4 = (const float4*)sB;
        #pragma unroll
        for (int k = 0; k < 32; k++) {
            float4 a = As4[k * 17 + ty];
            float4 b = Bs4[k * 17 + tx];
            acc0.x += a.x*b.x; acc0.y += a.x*b.y; acc0.z += a.x*b.z; acc0.w += a.x*b.w;
            acc1.x += a.y*b.x; acc1.y += a.y*b.y; acc1.z += a.y*b.z; acc1.w += a.y*b.w;
            acc2.x += a.z*b.x; acc2.y += a.z*b.y; acc2.z += a.z*b.z; acc2.w += a.z*b.w;
            acc3.x += a.w*b.x; acc3.y += a.w*b.y; acc3.z += a.w*b.z; acc3.w += a.w*b.w;
        }
        __syncthreads();
    }

    float4 b1 = __ldg((const float4*)&bi[n0 + tx * 4]);
    float4 b2 = __ldg((const float4*)&bh[n0 + tx * 4]);
    float4 bias = { b1.x + b2.x, b1.y + b2.y, b1.z + b2.z, b1.w + b2.w };

    float4 o;
    #define STORE_ROW(ACC, I) \
        o.x = ACC.x + bias.x; o.y = ACC.y + bias.y; o.z = ACC.z + bias.z; o.w = ACC.w + bias.w; \
        *(float4*)&C[(size_t)(m0 + ty * 4 + (I)) * GG + n0 + tx * 4] = o;
    STORE_ROW(acc0, 0) STORE_ROW(acc1, 1) STORE_ROW(acc2, 2) STORE_ROW(acc3, 3)
    #undef STORE_ROW
}

// ---------------------------------------------------------------------------
// Persistent recurrent kernel. 128 CTAs (1/SM), 256 threads.
// CTA owns 4 hidden units j (16 W_hh rows) kept in SMEM for all 2048 steps.
// Thread = (b, jj): 4 gate accumulators, cell state in register.
// h(t-1) staged per step: L2 (__ldcg) -> padded SMEM.
// ---------------------------------------------------------------------------
#define NCTA 128
#define WPAD 516                    // 512+4: conflict-free, 16B-aligned rows
#define REC_SMEM ((16 + 64) * WPAD * 4)   // 33KB W + 132KB h = 165,120 B

__device__ __forceinline__ void grid_bar()
{
    __threadfence();
    __syncthreads();
    if (threadIdx.x == 0) {
        unsigned gen = g_gen;
        if (atomicAdd(&g_count, 1u) == NCTA - 1u) {
            atomicExch(&g_count, 0u);
            __threadfence();
            g_gen = gen + 1u;
        } else {
            while (g_gen == gen) { }
        }
    }
    __syncthreads();
}

__global__ __launch_bounds__(256, 1) void lstm_rec(
    const float* __restrict__ xg, const float* __restrict__ Whh,
    float* __restrict__ H)
{
    extern __shared__ float sm[];
    float* sW = sm;                 // [16][WPAD], row index = g*4+jj
    float* sH = sm + 16 * WPAD;     // [64][WPAD]

    const int tid = threadIdx.x;
    const int j0 = blockIdx.x * 4;

    // Load this CTA's 16 W_hh rows once (resident for the whole sequence).
    for (int idx = tid; idx < 16 * 512; idx += 256) {
        int r = idx >> 9, k = idx & 511;
        int g = r >> 2, jj = r & 3;
        sW[r * WPAD + k] = __ldg(&Whh[(size_t)(g * HH + j0 + jj) * HH + k]);
    }

    const int b  = tid >> 2;
    const int jj = tid & 3;
    const int jg = j0 + jj;
    float c = 0.0f;

    const float4* w0 = (const float4*)(sW + (0  + jj) * WPAD);
    const float4* w1 = (const float4*)(sW + (4  + jj) * WPAD);
    const float4* w2 = (const float4*)(sW + (8  + jj) * WPAD);
    const float4* w3 = (const float4*)(sW + (12 + jj) * WPAD);
    const float4* hb = (const float4*)(sH + b * WPAD);
    float4* sH4 = (float4*)sH;

    for (int t = 0; t < TT; t++) {
        if (t > 0) {   // stage h(t-1) from L2 into SMEM (L1-bypassed: cross-SM data)
            const float4* hp = (const float4*)(H + (size_t)(t - 1) * BB * HH);
            #pragma unroll 4
            for (int i = tid; i < BB * 128; i += 256) {
                int row = i >> 7, q = i & 127;
                sH4[row * 129 + q] = __ldcg(hp + i);
            }
        }
        __syncthreads();

        const float* xr = xg + ((size_t)t * BB + b) * GG;
        float a0 = __ldg(xr + jg);
        float a1 = __ldg(xr + 512 + jg);
        float a2 = __ldg(xr + 1024 + jg);
        float a3 = __ldg(xr + 1536 + jg);

        if (t > 0) {
            #pragma unroll 4
            for (int k = 0; k < 128; k++) {
                float4 h4 = hb[k];
                float4 w;
                w = w0[k]; a0 += h4.x*w.x + h4.y*w.y + h4.z*w.z + h4.w*w.w;
                w = w1[k]; a1 += h4.x*w.x + h4.y*w.y + h4.z*w.z + h4.w*w.w;
                w = w2[k]; a2 += h4.x*w.x + h4.y*w.y + h4.z*w.z + h4.w*w.w;
                w = w3[k]; a3 += h4.x*w.x + h4.y*w.y + h4.z*w.z + h4.w*w.w;
            }
        }

        // PyTorch gate order i, f, g, o
        float ig = sigm(a0);
        float fg = sigm(a1);
        float gg = tanhf(a2);
        float og = sigm(a3);
        c = fg * c + ig * gg;
        float h = og * tanhf(c);
        H[((size_t)t * BB + b) * HH + jg] = h;

        grid_bar();
    }
}

// ---------------------------------------------------------------------------
// Output head: out[t,b] = sigmoid(dot(h2[t,b,:], W_out) + b_out). Warp/output.
// ---------------------------------------------------------------------------
__global__ __launch_bounds__(256) void out_proj(
    const float* __restrict__ H2, const float* __restrict__ Wout,
    const float* __restrict__ bout, float* __restrict__ out)
{
    int w = (blockIdx.x * blockDim.x + threadIdx.x) >> 5;
    int lane = threadIdx.x & 31;
    if (w >= TT * BB) return;
    const float4* h  = (const float4*)(H2 + (size_t)w * HH);
    const float4* wv = (const float4*)Wout;
    float acc = 0.0f;
    #pragma unroll
    for (int i = lane; i < 128; i += 32) {
        float4 a = __ldg(h + i);
        float4 b = __ldg(wv + i);
        acc += a.x*b.x + a.y*b.y + a.z*b.z + a.w*b.w;
    }
    #pragma unroll
    for (int off = 16; off; off >>= 1) acc += __shfl_xor_sync(0xffffffffu, acc, off);
    if (lane == 0) out[w] = 1.0f / (1.0f + expf(-(acc + __ldg(bout))));
}

// ---------------------------------------------------------------------------
extern "C" void kernel_launch(void* const* d_in, const int* in_sizes, int n_in,
                              void* d_out, int out_size)
{
    const float* x     = (const float*)d_in[0];
    const float* Wih1  = (const float*)d_in[1];
    const float* Whh1  = (const float*)d_in[2];
    const float* bih1  = (const float*)d_in[3];
    const float* bhh1  = (const float*)d_in[4];
    const float* Wih2  = (const float*)d_in[5];
    const float* Whh2  = (const float*)d_in[6];
    const float* bih2  = (const float*)d_in[7];
    const float* bhh2  = (const float*)d_in[8];
    const float* Wout  = (const float*)d_in[9];
    const float* bout  = (const float*)d_in[10];
    float* out = (float*)d_out;

    void *xg_p, *h1_p, *h2_p;
    cudaGetSymbolAddress(&xg_p, g_xg);
    cudaGetSymbolAddress(&h1_p, g_h1);
    cudaGetSymbolAddress(&h2_p, g_h2);
    float* xg = (float*)xg_p;
    float* h1 = (float*)h1_p;
    float* h2 = (float*)h2_p;

    cudaFuncSetAttribute(lstm_rec, cudaFuncAttributeMaxDynamicSharedMemorySize, REC_SMEM);

    dim3 ggrid(GG / 64, (TT * BB) / 64);   // (32, 2048)

    // Layer 1
    gemm_xg<<<ggrid, 256>>>(x, Wih1, bih1, bhh1, xg, 256);
    lstm_rec<<<NCTA, 256, REC_SMEM>>>(xg, Whh1, h1);
    // Layer 2 (XG buffer reused)
    gemm_xg<<<ggrid, 256>>>(h1, Wih2, bih2, bhh2, xg, 512);
    lstm_rec<<<NCTA, 256, REC_SMEM>>>(xg, Whh2, h2);
    // Head
    out_proj<<<(TT * BB * 32 + 255) / 256, 256>>>(h2, Wout, bout, out);
}

// round 3
// speedup vs baseline: 1.0382x; 1.0382x over previous
#include <cuda_runtime.h>
#include <math.h>

#define TT 2048
#define BB 64
#define HH 512
#define GG 2048   // 4*HH

// Scratch (module-load allocated). g_xg reused by both layers.
__device__ float g_xg[268435456];              // TT*BB*GG = 1 GB
__device__ float g_h1[134217728 / 2];          // TT*BB*HH floats
__device__ float g_h2[134217728 / 2];
__device__ unsigned g_count;
__device__ volatile unsigned g_gen;

typedef unsigned long long u64;

__device__ __forceinline__ float sigm(float x) { return 1.0f / (1.0f + expf(-x)); }

__device__ __forceinline__ u64 ffma2(u64 a, u64 b, u64 c) {
    u64 d;
    asm("fma.rn.f32x2 %0, %1, %2, %3;" : "=l"(d) : "l"(a), "l"(b), "l"(c));
    return d;
}
__device__ __forceinline__ float f2_lo(u64 v) { return __uint_as_float((unsigned)v); }
__device__ __forceinline__ float f2_hi(u64 v) { return __uint_as_float((unsigned)(v >> 32)); }
__device__ __forceinline__ float f2_sum(u64 v) { return f2_lo(v) + f2_hi(v); }

// ---------------------------------------------------------------------------
// GEMM: C[M x 2048] = A[M x K] * B[2048 x K]^T + bi[n] + bh[n]
// Tile 64x64, BK=32 (16 k-pairs), 256 threads, 4x4 per thread (n,m strided 16).
// SMEM holds k-PAIRS as u64 in [k2][m/n] layout (pitch 65 u64) so the inner
// loop runs packed fma.rn.f32x2 with zero splat overhead and no bank conflicts.
// ---------------------------------------------------------------------------
#define GP 65   // u64 pitch

__global__ __launch_bounds__(256) void gemm_xg(
    const float* __restrict__ A, const float* __restrict__ B,
    const float* __restrict__ bi, const float* __restrict__ bh,
    float* __restrict__ C, int K)
{
    __shared__ u64 sA[16 * GP];
    __shared__ u64 sB[16 * GP];
    float2* sA2 = (float2*)sA;
    float2* sB2 = (float2*)sB;

    const int tid = threadIdx.x;
    const int tx = tid & 15;        // n lane (cols n0 + tx + 16j)
    const int ty = tid >> 4;        // m lane (rows m0 + ty + 16i)
    const int m0 = blockIdx.y * 64;
    const int n0 = blockIdx.x * 64;
    const int r0 = tid >> 3;        // 0..31 (row within tile for loads)
    const int kq = tid & 7;         // float4 index within 32-k block

    u64 acc[4][4];
    #pragma unroll
    for (int i = 0; i < 4; i++)
        #pragma unroll
        for (int j = 0; j < 4; j++) acc[i][j] = 0ULL;

    for (int kb = 0; kb < K; kb += 32) {
        #pragma unroll
        for (int half = 0; half < 2; half++) {
            int r = r0 + half * 32;
            float4 av = __ldg((const float4*)&A[(size_t)(m0 + r) * K + kb + kq * 4]);
            float4 bv = __ldg((const float4*)&B[(size_t)(n0 + r) * K + kb + kq * 4]);
            sA2[(2*kq+0) * GP + r] = make_float2(av.x, av.y);
            sA2[(2*kq+1) * GP + r] = make_float2(av.z, av.w);
            sB2[(2*kq+0) * GP + r] = make_float2(bv.x, bv.y);
            sB2[(2*kq+1) * GP + r] = make_float2(bv.z, bv.w);
        }
        __syncthreads();
        #pragma unroll
        for (int k2 = 0; k2 < 16; k2++) {
            u64 a0 = sA[k2 * GP + ty];
            u64 a1 = sA[k2 * GP + ty + 16];
            u64 a2 = sA[k2 * GP + ty + 32];
            u64 a3 = sA[k2 * GP + ty + 48];
            u64 b0 = sB[k2 * GP + tx];
            u64 b1 = sB[k2 * GP + tx + 16];
            u64 b2 = sB[k2 * GP + tx + 32];
            u64 b3 = sB[k2 * GP + tx + 48];
            acc[0][0] = ffma2(a0, b0, acc[0][0]); acc[0][1] = ffma2(a0, b1, acc[0][1]);
            acc[0][2] = ffma2(a0, b2, acc[0][2]); acc[0][3] = ffma2(a0, b3, acc[0][3]);
            acc[1][0] = ffma2(a1, b0, acc[1][0]); acc[1][1] = ffma2(a1, b1, acc[1][1]);
            acc[1][2] = ffma2(a1, b2, acc[1][2]); acc[1][3] = ffma2(a1, b3, acc[1][3]);
            acc[2][0] = ffma2(a2, b0, acc[2][0]); acc[2][1] = ffma2(a2, b1, acc[2][1]);
            acc[2][2] = ffma2(a2, b2, acc[2][2]); acc[2][3] = ffma2(a2, b3, acc[2][3]);
            acc[3][0] = ffma2(a3, b0, acc[3][0]); acc[3][1] = ffma2(a3, b1, acc[3][1]);
            acc[3][2] = ffma2(a3, b2, acc[3][2]); acc[3][3] = ffma2(a3, b3, acc[3][3]);
        }
        __syncthreads();
    }

    float bias[4];
    #pragma unroll
    for (int j = 0; j < 4; j++) {
        int n = n0 + tx + 16 * j;
        bias[j] = __ldg(&bi[n]) + __ldg(&bh[n]);
    }
    #pragma unroll
    for (int i = 0; i < 4; i++) {
        int m = m0 + ty + 16 * i;
        #pragma unroll
        for (int j = 0; j < 4; j++) {
            int n = n0 + tx + 16 * j;
            C[(size_t)m * GG + n] = f2_sum(acc[i][j]) + bias[j];
        }
    }
}

// ---------------------------------------------------------------------------
// Persistent recurrent kernel. 128 CTAs (1/SM), 256 threads.
// CTA owns 4 hidden units j (16 W_hh rows, resident in SMEM for all steps).
// Thread = (b, jj). Inner dot runs packed fma.rn.f32x2 (8 chains).
// ---------------------------------------------------------------------------
#define NCTA 128
#define WPAD 516                    // 512+4: conflict-free, 16B-aligned rows
#define REC_SMEM ((16 + 64) * WPAD * 4)   // 165,120 B

__device__ __forceinline__ void grid_bar()
{
    __threadfence();
    __syncthreads();
    if (threadIdx.x == 0) {
        unsigned gen = g_gen;
        if (atomicAdd(&g_count, 1u) == NCTA - 1u) {
            atomicExch(&g_count, 0u);
            __threadfence();
            g_gen = gen + 1u;
        } else {
            while (g_gen == gen) { }
        }
    }
    __syncthreads();
}

__global__ __launch_bounds__(256, 1) void lstm_rec(
    const float* __restrict__ xg, const float* __restrict__ Whh,
    float* __restrict__ H)
{
    extern __shared__ float sm[];
    float* sW = sm;                 // [16][WPAD], row index = g*4+jj
    float* sH = sm + 16 * WPAD;     // [64][WPAD]

    const int tid = threadIdx.x;
    const int j0 = blockIdx.x * 4;

    for (int idx = tid; idx < 16 * 512; idx += 256) {
        int r = idx >> 9, k = idx & 511;
        int g = r >> 2, jj = r & 3;
        sW[r * WPAD + k] = __ldg(&Whh[(size_t)(g * HH + j0 + jj) * HH + k]);
    }

    const int b  = tid >> 2;
    const int jj = tid & 3;
    const int jg = j0 + jj;
    float c = 0.0f;

    const ulonglong2* w0 = (const ulonglong2*)(sW + (0  + jj) * WPAD);
    const ulonglong2* w1 = (const ulonglong2*)(sW + (4  + jj) * WPAD);
    const ulonglong2* w2 = (const ulonglong2*)(sW + (8  + jj) * WPAD);
    const ulonglong2* w3 = (const ulonglong2*)(sW + (12 + jj) * WPAD);
    const ulonglong2* hb = (const ulonglong2*)(sH + b * WPAD);
    float4* sH4 = (float4*)sH;

    for (int t = 0; t < TT; t++) {
        if (t > 0) {   // stage h(t-1) from L2 into SMEM
            const float4* hp = (const float4*)(H + (size_t)(t - 1) * BB * HH);
            #pragma unroll 4
            for (int i = tid; i < BB * 128; i += 256) {
                int row = i >> 7, q = i & 127;
                sH4[row * 129 + q] = __ldcg(hp + i);
            }
        }
        __syncthreads();

        const float* xr = xg + ((size_t)t * BB + b) * GG;
        float a0 = __ldg(xr + jg);
        float a1 = __ldg(xr + 512 + jg);
        float a2 = __ldg(xr + 1024 + jg);
        float a3 = __ldg(xr + 1536 + jg);

        if (t > 0) {
            u64 p0a = 0, p0b = 0, p1a = 0, p1b = 0;
            u64 p2a = 0, p2b = 0, p3a = 0, p3b = 0;
            #pragma unroll 4
            for (int k = 0; k < 128; k++) {
                ulonglong2 h2 = hb[k];
                ulonglong2 w;
                w = w0[k]; p0a = ffma2(h2.x, w.x, p0a); p0b = ffma2(h2.y, w.y, p0b);
                w = w1[k]; p1a = ffma2(h2.x, w.x, p1a); p1b = ffma2(h2.y, w.y, p1b);
                w = w2[k]; p2a = ffma2(h2.x, w.x, p2a); p2b = ffma2(h2.y, w.y, p2b);
                w = w3[k]; p3a = ffma2(h2.x, w.x, p3a); p3b = ffma2(h2.y, w.y, p3b);
            }
            a0 += f2_sum(p0a) + f2_sum(p0b);
            a1 += f2_sum(p1a) + f2_sum(p1b);
            a2 += f2_sum(p2a) + f2_sum(p2b);
            a3 += f2_sum(p3a) + f2_sum(p3b);
        }

        // PyTorch gate order i, f, g, o
        float ig = sigm(a0);
        float fg = sigm(a1);
        float gg = tanhf(a2);
        float og = sigm(a3);
        c = fg * c + ig * gg;
        float h = og * tanhf(c);
        H[((size_t)t * BB + b) * HH + jg] = h;

        grid_bar();
    }
}

// ---------------------------------------------------------------------------
// Output head: out[t,b] = sigmoid(dot(h2[t,b,:], W_out) + b_out). Warp/output.
// ---------------------------------------------------------------------------
__global__ __launch_bounds__(256) void out_proj(
    const float* __restrict__ H2, const float* __restrict__ Wout,
    const float* __restrict__ bout, float* __restrict__ out)
{
    int w = (blockIdx.x * blockDim.x + threadIdx.x) >> 5;
    int lane = threadIdx.x & 31;
    if (w >= TT * BB) return;
    const float4* h  = (const float4*)(H2 + (size_t)w * HH);
    const float4* wv = (const float4*)Wout;
    float acc = 0.0f;
    #pragma unroll
    for (int i = lane; i < 128; i += 32) {
        float4 a = __ldg(h + i);
        float4 b = __ldg(wv + i);
        acc += a.x*b.x + a.y*b.y + a.z*b.z + a.w*b.w;
    }
    #pragma unroll
    for (int off = 16; off; off >>= 1) acc += __shfl_xor_sync(0xffffffffu, acc, off);
    if (lane == 0) out[w] = 1.0f / (1.0f + expf(-(acc + __ldg(bout))));
}

// ---------------------------------------------------------------------------
extern "C" void kernel_launch(void* const* d_in, const int* in_sizes, int n_in,
                              void* d_out, int out_size)
{
    const float* x     = (const float*)d_in[0];
    const float* Wih1  = (const float*)d_in[1];
    const float* Whh1  = (const float*)d_in[2];
    const float* bih1  = (const float*)d_in[3];
    const float* bhh1  = (const float*)d_in[4];
    const float* Wih2  = (const float*)d_in[5];
    const float* Whh2  = (const float*)d_in[6];
    const float* bih2  = (const float*)d_in[7];
    const float* bhh2  = (const float*)d_in[8];
    const float* Wout  = (const float*)d_in[9];
    const float* bout  = (const float*)d_in[10];
    float* out = (float*)d_out;

    void *xg_p, *h1_p, *h2_p;
    cudaGetSymbolAddress(&xg_p, g_xg);
    cudaGetSymbolAddress(&h1_p, g_h1);
    cudaGetSymbolAddress(&h2_p, g_h2);
    float* xg = (float*)xg_p;
    float* h1 = (float*)h1_p;
    float* h2 = (float*)h2_p;

    cudaFuncSetAttribute(lstm_rec, cudaFuncAttributeMaxDynamicSharedMemorySize, REC_SMEM);

    dim3 ggrid(GG / 64, (TT * BB) / 64);   // (32, 2048)

    // Layer 1
    gemm_xg<<<ggrid, 256>>>(x, Wih1, bih1, bhh1, xg, 256);
    lstm_rec<<<NCTA, 256, REC_SMEM>>>(xg, Whh1, h1);
    // Layer 2 (XG buffer reused)
    gemm_xg<<<ggrid, 256>>>(h1, Wih2, bih2, bhh2, xg, 512);
    lstm_rec<<<NCTA, 256, REC_SMEM>>>(xg, Whh2, h2);
    // Head
    out_proj<<<(TT * BB * 32 + 255) / 256, 256>>>(h2, Wout, bout, out);
}

// round 4
// speedup vs baseline: 1.2501x; 1.2041x over previous
#include <cuda_runtime.h>
#include <math.h>

#define TT 2048
#define BB 64
#define HH 512
#define GG 2048   // 4*HH

// Scratch (module-load allocated). g_xg reused by both layers.
__device__ float g_xg[268435456];              // TT*BB*GG = 1 GB
__device__ float g_h1[67108864];               // TT*BB*HH floats
__device__ float g_h2[67108864];
__device__ unsigned g_grp[16 * 64];            // group counters, 256B apart
__device__ unsigned g_root;
__device__ volatile unsigned g_gen;

typedef unsigned long long u64;

__device__ __forceinline__ float sigm(float x) { return 1.0f / (1.0f + expf(-x)); }

__device__ __forceinline__ u64 ffma2(u64 a, u64 b, u64 c) {
    u64 d;
    asm("fma.rn.f32x2 %0, %1, %2, %3;" : "=l"(d) : "l"(a), "l"(b), "l"(c));
    return d;
}
__device__ __forceinline__ u64 addf2(u64 a, u64 b) {
    u64 d;
    asm("add.rn.f32x2 %0, %1, %2;" : "=l"(d) : "l"(a), "l"(b));
    return d;
}
__device__ __forceinline__ float f2_sum(u64 v) {
    return __uint_as_float((unsigned)v) + __uint_as_float((unsigned)(v >> 32));
}

// ---------------------------------------------------------------------------
// GEMM: C[M x 2048] = A[M x K] * B[2048 x K]^T + bi[n] + bh[n]   (unchanged R3)
// ---------------------------------------------------------------------------
#define GP 65   // u64 pitch

__global__ __launch_bounds__(256) void gemm_xg(
    const float* __restrict__ A, const float* __restrict__ B,
    const float* __restrict__ bi, const float* __restrict__ bh,
    float* __restrict__ C, int K)
{
    __shared__ u64 sA[16 * GP];
    __shared__ u64 sB[16 * GP];
    float2* sA2 = (float2*)sA;
    float2* sB2 = (float2*)sB;

    const int tid = threadIdx.x;
    const int tx = tid & 15;
    const int ty = tid >> 4;
    const int m0 = blockIdx.y * 64;
    const int n0 = blockIdx.x * 64;
    const int r0 = tid >> 3;
    const int kq = tid & 7;

    u64 acc[4][4];
    #pragma unroll
    for (int i = 0; i < 4; i++)
        #pragma unroll
        for (int j = 0; j < 4; j++) acc[i][j] = 0ULL;

    for (int kb = 0; kb < K; kb += 32) {
        #pragma unroll
        for (int half = 0; half < 2; half++) {
            int r = r0 + half * 32;
            float4 av = __ldg((const float4*)&A[(size_t)(m0 + r) * K + kb + kq * 4]);
            float4 bv = __ldg((const float4*)&B[(size_t)(n0 + r) * K + kb + kq * 4]);
            sA2[(2*kq+0) * GP + r] = make_float2(av.x, av.y);
            sA2[(2*kq+1) * GP + r] = make_float2(av.z, av.w);
            sB2[(2*kq+0) * GP + r] = make_float2(bv.x, bv.y);
            sB2[(2*kq+1) * GP + r] = make_float2(bv.z, bv.w);
        }
        __syncthreads();
        #pragma unroll
        for (int k2 = 0; k2 < 16; k2++) {
            u64 a0 = sA[k2 * GP + ty];
            u64 a1 = sA[k2 * GP + ty + 16];
            u64 a2 = sA[k2 * GP + ty + 32];
            u64 a3 = sA[k2 * GP + ty + 48];
            u64 b0 = sB[k2 * GP + tx];
            u64 b1 = sB[k2 * GP + tx + 16];
            u64 b2 = sB[k2 * GP + tx + 32];
            u64 b3 = sB[k2 * GP + tx + 48];
            acc[0][0] = ffma2(a0, b0, acc[0][0]); acc[0][1] = ffma2(a0, b1, acc[0][1]);
            acc[0][2] = ffma2(a0, b2, acc[0][2]); acc[0][3] = ffma2(a0, b3, acc[0][3]);
            acc[1][0] = ffma2(a1, b0, acc[1][0]); acc[1][1] = ffma2(a1, b1, acc[1][1]);
            acc[1][2] = ffma2(a1, b2, acc[1][2]); acc[1][3] = ffma2(a1, b3, acc[1][3]);
            acc[2][0] = ffma2(a2, b0, acc[2][0]); acc[2][1] = ffma2(a2, b1, acc[2][1]);
            acc[2][2] = ffma2(a2, b2, acc[2][2]); acc[2][3] = ffma2(a2, b3, acc[2][3]);
            acc[3][0] = ffma2(a3, b0, acc[3][0]); acc[3][1] = ffma2(a3, b1, acc[3][1]);
            acc[3][2] = ffma2(a3, b2, acc[3][2]); acc[3][3] = ffma2(a3, b3, acc[3][3]);
        }
        __syncthreads();
    }

    float bias[4];
    #pragma unroll
    for (int j = 0; j < 4; j++) {
        int n = n0 + tx + 16 * j;
        bias[j] = __ldg(&bi[n]) + __ldg(&bh[n]);
    }
    #pragma unroll
    for (int i = 0; i < 4; i++) {
        int m = m0 + ty + 16 * i;
        #pragma unroll
        for (int j = 0; j < 4; j++) {
            int n = n0 + tx + 16 * j;
            C[(size_t)m * GG + n] = f2_sum(acc[i][j]) + bias[j];
        }
    }
}

// ---------------------------------------------------------------------------
// Persistent recurrent kernel. 128 CTAs (1/SM), 256 threads.
// CTA owns 4 hidden units (16 W_hh rows resident in SMEM).
// K-SPLIT: threads 0-127 do k[0,256), threads 128-255 do k[256,512);
// thread tile = 2 batches x 4 gates (8 outputs), partials merged via SMEM.
// Crossbar cost: 6 LDS.128 per 32 MACs (was 5 per 16) -> 12.3K cyc/step.
// ---------------------------------------------------------------------------
#define NCTA 128
#define WPAD 516
#define SW_FLOATS (16 * WPAD)          // 8256
#define SH_FLOATS (64 * WPAD)          // 33024
#define REC_SMEM ((SW_FLOATS + SH_FLOATS) * 4 + 1024 * 8)   // 173,312 B

__device__ __forceinline__ void grid_bar()
{
    __threadfence();
    __syncthreads();
    if (threadIdx.x == 0) {
        unsigned gen = g_gen;
        unsigned grp = blockIdx.x >> 3;                 // 16 groups of 8
        if (atomicAdd(&g_grp[grp * 64], 1u) == 7u) {
            atomicExch(&g_grp[grp * 64], 0u);
            if (atomicAdd(&g_root, 1u) == 15u) {
                atomicExch(&g_root, 0u);
                __threadfence();
                g_gen = gen + 1u;
            }
        }
        while (g_gen == gen) { }
    }
    __syncthreads();
}

__global__ __launch_bounds__(256, 1) void lstm_rec(
    const float* __restrict__ xg, const float* __restrict__ Whh,
    float* __restrict__ H)
{
    extern __shared__ float sm[];
    float* sW = sm;                         // [16][WPAD]
    float* sH = sm + SW_FLOATS;             // [64][WPAD]
    u64*   sR = (u64*)(sm + SW_FLOATS + SH_FLOATS);   // [128][8] partials
    float4* sH4 = (float4*)sH;              // pitch 129 float4

    const int tid = threadIdx.x;
    const int j0 = blockIdx.x * 4;

    // Load this CTA's 16 W_hh rows once.
    for (int idx = tid; idx < 16 * 512; idx += 256) {
        int r = idx >> 9, k = idx & 511;
        int g = r >> 2, jj = r & 3;
        sW[r * WPAD + k] = __ldg(&Whh[(size_t)(g * HH + j0 + jj) * HH + k]);
    }

    const int kh = tid >> 7;                // k-half: 0 or 1
    const int lo = tid & 127;
    const int p  = lo >> 2;                 // 0..31 batch-pair
    const int jj = lo & 3;
    const int b0 = 2 * p, b1 = 2 * p + 1;
    const int jg = j0 + jj;
    const int kbase = kh * 256;

    const ulonglong2* w0 = (const ulonglong2*)(sW + (0  + jj) * WPAD + kbase);
    const ulonglong2* w1 = (const ulonglong2*)(sW + (4  + jj) * WPAD + kbase);
    const ulonglong2* w2 = (const ulonglong2*)(sW + (8  + jj) * WPAD + kbase);
    const ulonglong2* w3 = (const ulonglong2*)(sW + (12 + jj) * WPAD + kbase);
    const ulonglong2* hA = (const ulonglong2*)(sH + b0 * WPAD + kbase);
    const ulonglong2* hB = (const ulonglong2*)(sH + b1 * WPAD + kbase);

    float c0 = 0.0f, c1 = 0.0f;

    for (int t = 0; t < TT; t++) {
        // Hoisted xg loads (DRAM latency hidden behind staging).
        float x00=0, x10=0, x20=0, x30=0, x01=0, x11=0, x21=0, x31=0;
        if (kh == 0) {
            const float* xr0 = xg + ((size_t)t * BB + b0) * GG + jg;
            const float* xr1 = xg + ((size_t)t * BB + b1) * GG + jg;
            x00 = __ldg(xr0);        x10 = __ldg(xr0 + 512);
            x20 = __ldg(xr0 + 1024); x30 = __ldg(xr0 + 1536);
            x01 = __ldg(xr1);        x11 = __ldg(xr1 + 512);
            x21 = __ldg(xr1 + 1024); x31 = __ldg(xr1 + 1536);
        }

        if (t > 0) {   // stage h(t-1) from L2 into SMEM
            const float4* hp = (const float4*)(H + (size_t)(t - 1) * BB * HH);
            #pragma unroll 4
            for (int i = tid; i < BB * 128; i += 256) {
                int row = i >> 7, q = i & 127;
                sH4[row * 129 + q] = __ldcg(hp + i);
            }
        }
        __syncthreads();

        u64 a00=0, a10=0, a20=0, a30=0;     // gates i,f,g,o for b0
        u64 a01=0, a11=0, a21=0, a31=0;     // for b1
        if (t > 0) {
            #pragma unroll 8
            for (int c = 0; c < 64; c++) {
                ulonglong2 h0 = hA[c];
                ulonglong2 h1 = hB[c];
                ulonglong2 w;
                w = w0[c];
                a00 = ffma2(h0.x, w.x, a00); a00 = ffma2(h0.y, w.y, a00);
                a01 = ffma2(h1.x, w.x, a01); a01 = ffma2(h1.y, w.y, a01);
                w = w1[c];
                a10 = ffma2(h0.x, w.x, a10); a10 = ffma2(h0.y, w.y, a10);
                a11 = ffma2(h1.x, w.x, a11); a11 = ffma2(h1.y, w.y, a11);
                w = w2[c];
                a20 = ffma2(h0.x, w.x, a20); a20 = ffma2(h0.y, w.y, a20);
                a21 = ffma2(h1.x, w.x, a21); a21 = ffma2(h1.y, w.y, a21);
                w = w3[c];
                a30 = ffma2(h0.x, w.x, a30); a30 = ffma2(h0.y, w.y, a30);
                a31 = ffma2(h1.x, w.x, a31); a31 = ffma2(h1.y, w.y, a31);
            }
            if (kh) {   // upper k-half publishes partials
                u64* dst = sR + lo * 8;
                dst[0] = a00; dst[1] = a10; dst[2] = a20; dst[3] = a30;
                dst[4] = a01; dst[5] = a11; dst[6] = a21; dst[7] = a31;
            }
        }
        __syncthreads();

        if (kh == 0) {
            if (t > 0) {
                const u64* src = sR + lo * 8;
                a00 = addf2(a00, src[0]); a10 = addf2(a10, src[1]);
                a20 = addf2(a20, src[2]); a30 = addf2(a30, src[3]);
                a01 = addf2(a01, src[4]); a11 = addf2(a11, src[5]);
                a21 = addf2(a21, src[6]); a31 = addf2(a31, src[7]);
            }
            // batch b0
            {
                float gi = sigm(x00 + f2_sum(a00));
                float gf = sigm(x10 + f2_sum(a10));
                float gg = tanhf(x20 + f2_sum(a20));
                float go = sigm(x30 + f2_sum(a30));
                c0 = gf * c0 + gi * gg;
                H[((size_t)t * BB + b0) * HH + jg] = go * tanhf(c0);
            }
            // batch b1
            {
                float gi = sigm(x01 + f2_sum(a01));
                float gf = sigm(x11 + f2_sum(a11));
                float gg = tanhf(x21 + f2_sum(a21));
                float go = sigm(x31 + f2_sum(a31));
                c1 = gf * c1 + gi * gg;
                H[((size_t)t * BB + b1) * HH + jg] = go * tanhf(c1);
            }
        }

        grid_bar();
    }
}

// ---------------------------------------------------------------------------
// Output head: out[t,b] = sigmoid(dot(h2[t,b,:], W_out) + b_out). Warp/output.
// ---------------------------------------------------------------------------
__global__ __launch_bounds__(256) void out_proj(
    const float* __restrict__ H2, const float* __restrict__ Wout,
    const float* __restrict__ bout, float* __restrict__ out)
{
    int w = (blockIdx.x * blockDim.x + threadIdx.x) >> 5;
    int lane = threadIdx.x & 31;
    if (w >= TT * BB) return;
    const float4* h  = (const float4*)(H2 + (size_t)w * HH);
    const float4* wv = (const float4*)Wout;
    float acc = 0.0f;
    #pragma unroll
    for (int i = lane; i < 128; i += 32) {
        float4 a = __ldg(h + i);
        float4 b = __ldg(wv + i);
        acc += a.x*b.x + a.y*b.y + a.z*b.z + a.w*b.w;
    }
    #pragma unroll
    for (int off = 16; off; off >>= 1) acc += __shfl_xor_sync(0xffffffffu, acc, off);
    if (lane == 0) out[w] = 1.0f / (1.0f + expf(-(acc + __ldg(bout))));
}

// ---------------------------------------------------------------------------
extern "C" void kernel_launch(void* const* d_in, const int* in_sizes, int n_in,
                              void* d_out, int out_size)
{
    const float* x     = (const float*)d_in[0];
    const float* Wih1  = (const float*)d_in[1];
    const float* Whh1  = (const float*)d_in[2];
    const float* bih1  = (const float*)d_in[3];
    const float* bhh1  = (const float*)d_in[4];
    const float* Wih2  = (const float*)d_in[5];
    const float* Whh2  = (const float*)d_in[6];
    const float* bih2  = (const float*)d_in[7];
    const float* bhh2  = (const float*)d_in[8];
    const float* Wout  = (const float*)d_in[9];
    const float* bout  = (const float*)d_in[10];
    float* out = (float*)d_out;

    void *xg_p, *h1_p, *h2_p;
    cudaGetSymbolAddress(&xg_p, g_xg);
    cudaGetSymbolAddress(&h1_p, g_h1);
    cudaGetSymbolAddress(&h2_p, g_h2);
    float* xg = (float*)xg_p;
    float* h1 = (float*)h1_p;
    float* h2 = (float*)h2_p;

    cudaFuncSetAttribute(lstm_rec, cudaFuncAttributeMaxDynamicSharedMemorySize, REC_SMEM);

    dim3 ggrid(GG / 64, (TT * BB) / 64);   // (32, 2048)

    // Layer 1
    gemm_xg<<<ggrid, 256>>>(x, Wih1, bih1, bhh1, xg, 256);
    lstm_rec<<<NCTA, 256, REC_SMEM>>>(xg, Whh1, h1);
    // Layer 2 (XG buffer reused)
    gemm_xg<<<ggrid, 256>>>(h1, Wih2, bih2, bhh2, xg, 512);
    lstm_rec<<<NCTA, 256, REC_SMEM>>>(xg, Whh2, h2);
    // Head
    out_proj<<<(TT * BB * 32 + 255) / 256, 256>>>(h2, Wout, bout, out);
}

// round 5
// speedup vs baseline: 1.2515x; 1.0011x over previous
#include <cuda_runtime.h>
#include <math.h>

#define TT 2048
#define BB 64
#define HH 512
#define GG 2048   // 4*HH

// Scratch (module-load allocated). g_xg reused by both layers.
__device__ float g_xg[268435456];              // TT*BB*GG = 1 GB
__device__ float g_h1[67108864];               // TT*BB*HH floats
__device__ float g_h2[67108864];
__device__ unsigned g_grp[16 * 64];            // group counters, 256B apart
__device__ unsigned g_root;
__device__ volatile unsigned g_gen;

typedef unsigned long long u64;

__device__ __forceinline__ float sigm(float x) { return 1.0f / (1.0f + expf(-x)); }

__device__ __forceinline__ u64 ffma2(u64 a, u64 b, u64 c) {
    u64 d;
    asm("fma.rn.f32x2 %0, %1, %2, %3;" : "=l"(d) : "l"(a), "l"(b), "l"(c));
    return d;
}
__device__ __forceinline__ u64 addf2(u64 a, u64 b) {
    u64 d;
    asm("add.rn.f32x2 %0, %1, %2;" : "=l"(d) : "l"(a), "l"(b));
    return d;
}
__device__ __forceinline__ float f2_sum(u64 v) {
    return __uint_as_float((unsigned)v) + __uint_as_float((unsigned)(v >> 32));
}

// ---------------------------------------------------------------------------
// GEMM: C[M x 2048] = A[M x K] * B[2048 x K]^T + bi[n] + bh[n]   (unchanged R3)
// ---------------------------------------------------------------------------
#define GP 65   // u64 pitch

__global__ __launch_bounds__(256) void gemm_xg(
    const float* __restrict__ A, const float* __restrict__ B,
    const float* __restrict__ bi, const float* __restrict__ bh,
    float* __restrict__ C, int K)
{
    __shared__ u64 sA[16 * GP];
    __shared__ u64 sB[16 * GP];
    float2* sA2 = (float2*)sA;
    float2* sB2 = (float2*)sB;

    const int tid = threadIdx.x;
    const int tx = tid & 15;
    const int ty = tid >> 4;
    const int m0 = blockIdx.y * 64;
    const int n0 = blockIdx.x * 64;
    const int r0 = tid >> 3;
    const int kq = tid & 7;

    u64 acc[4][4];
    #pragma unroll
    for (int i = 0; i < 4; i++)
        #pragma unroll
        for (int j = 0; j < 4; j++) acc[i][j] = 0ULL;

    for (int kb = 0; kb < K; kb += 32) {
        #pragma unroll
        for (int half = 0; half < 2; half++) {
            int r = r0 + half * 32;
            float4 av = __ldg((const float4*)&A[(size_t)(m0 + r) * K + kb + kq * 4]);
            float4 bv = __ldg((const float4*)&B[(size_t)(n0 + r) * K + kb + kq * 4]);
            sA2[(2*kq+0) * GP + r] = make_float2(av.x, av.y);
            sA2[(2*kq+1) * GP + r] = make_float2(av.z, av.w);
            sB2[(2*kq+0) * GP + r] = make_float2(bv.x, bv.y);
            sB2[(2*kq+1) * GP + r] = make_float2(bv.z, bv.w);
        }
        __syncthreads();
        #pragma unroll
        for (int k2 = 0; k2 < 16; k2++) {
            u64 a0 = sA[k2 * GP + ty];
            u64 a1 = sA[k2 * GP + ty + 16];
            u64 a2 = sA[k2 * GP + ty + 32];
            u64 a3 = sA[k2 * GP + ty + 48];
            u64 b0 = sB[k2 * GP + tx];
            u64 b1 = sB[k2 * GP + tx + 16];
            u64 b2 = sB[k2 * GP + tx + 32];
            u64 b3 = sB[k2 * GP + tx + 48];
            acc[0][0] = ffma2(a0, b0, acc[0][0]); acc[0][1] = ffma2(a0, b1, acc[0][1]);
            acc[0][2] = ffma2(a0, b2, acc[0][2]); acc[0][3] = ffma2(a0, b3, acc[0][3]);
            acc[1][0] = ffma2(a1, b0, acc[1][0]); acc[1][1] = ffma2(a1, b1, acc[1][1]);
            acc[1][2] = ffma2(a1, b2, acc[1][2]); acc[1][3] = ffma2(a1, b3, acc[1][3]);
            acc[2][0] = ffma2(a2, b0, acc[2][0]); acc[2][1] = ffma2(a2, b1, acc[2][1]);
            acc[2][2] = ffma2(a2, b2, acc[2][2]); acc[2][3] = ffma2(a2, b3, acc[2][3]);
            acc[3][0] = ffma2(a3, b0, acc[3][0]); acc[3][1] = ffma2(a3, b1, acc[3][1]);
            acc[3][2] = ffma2(a3, b2, acc[3][2]); acc[3][3] = ffma2(a3, b3, acc[3][3]);
        }
        __syncthreads();
    }

    float bias[4];
    #pragma unroll
    for (int j = 0; j < 4; j++) {
        int n = n0 + tx + 16 * j;
        bias[j] = __ldg(&bi[n]) + __ldg(&bh[n]);
    }
    #pragma unroll
    for (int i = 0; i < 4; i++) {
        int m = m0 + ty + 16 * i;
        #pragma unroll
        for (int j = 0; j < 4; j++) {
            int n = n0 + tx + 16 * j;
            C[(size_t)m * GG + n] = f2_sum(acc[i][j]) + bias[j];
        }
    }
}

// ---------------------------------------------------------------------------
// Persistent recurrent kernel. 128 CTAs (1/SM), 256 threads.
// CTA owns 4 hidden units (16 W_hh rows resident in SMEM).
// K-SPLIT: threads 0-127 do k[0,256), threads 128-255 do k[256,512);
// thread tile = 2 batches x 4 gates (8 outputs), partials merged via SMEM.
// Crossbar cost: 6 LDS.128 per 32 MACs (was 5 per 16) -> 12.3K cyc/step.
// ---------------------------------------------------------------------------
#define NCTA 128
#define WPAD 516
#define SW_FLOATS (16 * WPAD)          // 8256
#define SH_FLOATS (64 * WPAD)          // 33024
#define REC_SMEM ((SW_FLOATS + SH_FLOATS) * 4 + 1024 * 8)   // 173,312 B

__device__ __forceinline__ void grid_bar()
{
    __threadfence();
    __syncthreads();
    if (threadIdx.x == 0) {
        unsigned gen = g_gen;
        unsigned grp = blockIdx.x >> 3;                 // 16 groups of 8
        if (atomicAdd(&g_grp[grp * 64], 1u) == 7u) {
            atomicExch(&g_grp[grp * 64], 0u);
            if (atomicAdd(&g_root, 1u) == 15u) {
                atomicExch(&g_root, 0u);
                __threadfence();
                g_gen = gen + 1u;
            }
        }
        while (g_gen == gen) { }
    }
    __syncthreads();
}

__global__ __launch_bounds__(256, 1) void lstm_rec(
    const float* __restrict__ xg, const float* __restrict__ Whh,
    float* __restrict__ H)
{
    extern __shared__ float sm[];
    float* sW = sm;                         // [16][WPAD]
    float* sH = sm + SW_FLOATS;             // [64][WPAD]
    u64*   sR = (u64*)(sm + SW_FLOATS + SH_FLOATS);   // [128][8] partials
    float4* sH4 = (float4*)sH;              // pitch 129 float4

    const int tid = threadIdx.x;
    const int j0 = blockIdx.x * 4;

    // Load this CTA's 16 W_hh rows once.
    for (int idx = tid; idx < 16 * 512; idx += 256) {
        int r = idx >> 9, k = idx & 511;
        int g = r >> 2, jj = r & 3;
        sW[r * WPAD + k] = __ldg(&Whh[(size_t)(g * HH + j0 + jj) * HH + k]);
    }

    const int kh = tid >> 7;                // k-half: 0 or 1
    const int lo = tid & 127;
    const int p  = lo >> 2;                 // 0..31 batch-pair
    const int jj = lo & 3;
    const int b0 = 2 * p, b1 = 2 * p + 1;
    const int jg = j0 + jj;
    const int kbase = kh * 256;

    const ulonglong2* w0 = (const ulonglong2*)(sW + (0  + jj) * WPAD + kbase);
    const ulonglong2* w1 = (const ulonglong2*)(sW + (4  + jj) * WPAD + kbase);
    const ulonglong2* w2 = (const ulonglong2*)(sW + (8  + jj) * WPAD + kbase);
    const ulonglong2* w3 = (const ulonglong2*)(sW + (12 + jj) * WPAD + kbase);
    const ulonglong2* hA = (const ulonglong2*)(sH + b0 * WPAD + kbase);
    const ulonglong2* hB = (const ulonglong2*)(sH + b1 * WPAD + kbase);

    float c0 = 0.0f, c1 = 0.0f;

    for (int t = 0; t < TT; t++) {
        // Hoisted xg loads (DRAM latency hidden behind staging).
        float x00=0, x10=0, x20=0, x30=0, x01=0, x11=0, x21=0, x31=0;
        if (kh == 0) {
            const float* xr0 = xg + ((size_t)t * BB + b0) * GG + jg;
            const float* xr1 = xg + ((size_t)t * BB + b1) * GG + jg;
            x00 = __ldg(xr0);        x10 = __ldg(xr0 + 512);
            x20 = __ldg(xr0 + 1024); x30 = __ldg(xr0 + 1536);
            x01 = __ldg(xr1);        x11 = __ldg(xr1 + 512);
            x21 = __ldg(xr1 + 1024); x31 = __ldg(xr1 + 1536);
        }

        if (t > 0) {   // stage h(t-1) from L2 into SMEM
            const float4* hp = (const float4*)(H + (size_t)(t - 1) * BB * HH);
            #pragma unroll 4
            for (int i = tid; i < BB * 128; i += 256) {
                int row = i >> 7, q = i & 127;
                sH4[row * 129 + q] = __ldcg(hp + i);
            }
        }
        __syncthreads();

        u64 a00=0, a10=0, a20=0, a30=0;     // gates i,f,g,o for b0
        u64 a01=0, a11=0, a21=0, a31=0;     // for b1
        if (t > 0) {
            #pragma unroll 8
            for (int c = 0; c < 64; c++) {
                ulonglong2 h0 = hA[c];
                ulonglong2 h1 = hB[c];
                ulonglong2 w;
                w = w0[c];
                a00 = ffma2(h0.x, w.x, a00); a00 = ffma2(h0.y, w.y, a00);
                a01 = ffma2(h1.x, w.x, a01); a01 = ffma2(h1.y, w.y, a01);
                w = w1[c];
                a10 = ffma2(h0.x, w.x, a10); a10 = ffma2(h0.y, w.y, a10);
                a11 = ffma2(h1.x, w.x, a11); a11 = ffma2(h1.y, w.y, a11);
                w = w2[c];
                a20 = ffma2(h0.x, w.x, a20); a20 = ffma2(h0.y, w.y, a20);
                a21 = ffma2(h1.x, w.x, a21); a21 = ffma2(h1.y, w.y, a21);
                w = w3[c];
                a30 = ffma2(h0.x, w.x, a30); a30 = ffma2(h0.y, w.y, a30);
                a31 = ffma2(h1.x, w.x, a31); a31 = ffma2(h1.y, w.y, a31);
            }
            if (kh) {   // upper k-half publishes partials
                u64* dst = sR + lo * 8;
                dst[0] = a00; dst[1] = a10; dst[2] = a20; dst[3] = a30;
                dst[4] = a01; dst[5] = a11; dst[6] = a21; dst[7] = a31;
            }
        }
        __syncthreads();

        if (kh == 0) {
            if (t > 0) {
                const u64* src = sR + lo * 8;
                a00 = addf2(a00, src[0]); a10 = addf2(a10, src[1]);
                a20 = addf2(a20, src[2]); a30 = addf2(a30, src[3]);
                a01 = addf2(a01, src[4]); a11 = addf2(a11, src[5]);
                a21 = addf2(a21, src[6]); a31 = addf2(a31, src[7]);
            }
            // batch b0
            {
                float gi = sigm(x00 + f2_sum(a00));
                float gf = sigm(x10 + f2_sum(a10));
                float gg = tanhf(x20 + f2_sum(a20));
                float go = sigm(x30 + f2_sum(a30));
                c0 = gf * c0 + gi * gg;
                H[((size_t)t * BB + b0) * HH + jg] = go * tanhf(c0);
            }
            // batch b1
            {
                float gi = sigm(x01 + f2_sum(a01));
                float gf = sigm(x11 + f2_sum(a11));
                float gg = tanhf(x21 + f2_sum(a21));
                float go = sigm(x31 + f2_sum(a31));
                c1 = gf * c1 + gi * gg;
                H[((size_t)t * BB + b1) * HH + jg] = go * tanhf(c1);
            }
        }

        grid_bar();
    }
}

// ---------------------------------------------------------------------------
// Output head: out[t,b] = sigmoid(dot(h2[t,b,:], W_out) + b_out). Warp/output.
// ---------------------------------------------------------------------------
__global__ __launch_bounds__(256) void out_proj(
    const float* __restrict__ H2, const float* __restrict__ Wout,
    const float* __restrict__ bout, float* __restrict__ out)
{
    int w = (blockIdx.x * blockDim.x + threadIdx.x) >> 5;
    int lane = threadIdx.x & 31;
    if (w >= TT * BB) return;
    const float4* h  = (const float4*)(H2 + (size_t)w * HH);
    const float4* wv = (const float4*)Wout;
    float acc = 0.0f;
    #pragma unroll
    for (int i = lane; i < 128; i += 32) {
        float4 a = __ldg(h + i);
        float4 b = __ldg(wv + i);
        acc += a.x*b.x + a.y*b.y + a.z*b.z + a.w*b.w;
    }
    #pragma unroll
    for (int off = 16; off; off >>= 1) acc += __shfl_xor_sync(0xffffffffu, acc, off);
    if (lane == 0) out[w] = 1.0f / (1.0f + expf(-(acc + __ldg(bout))));
}

// ---------------------------------------------------------------------------
extern "C" void kernel_launch(void* const* d_in, const int* in_sizes, int n_in,
                              void* d_out, int out_size)
{
    const float* x     = (const float*)d_in[0];
    const float* Wih1  = (const float*)d_in[1];
    const float* Whh1  = (const float*)d_in[2];
    const float* bih1  = (const float*)d_in[3];
    const float* bhh1  = (const float*)d_in[4];
    const float* Wih2  = (const float*)d_in[5];
    const float* Whh2  = (const float*)d_in[6];
    const float* bih2  = (const float*)d_in[7];
    const float* bhh2  = (const float*)d_in[8];
    const float* Wout  = (const float*)d_in[9];
    const float* bout  = (const float*)d_in[10];
    float* out = (float*)d_out;

    void *xg_p, *h1_p, *h2_p;
    cudaGetSymbolAddress(&xg_p, g_xg);
    cudaGetSymbolAddress(&h1_p, g_h1);
    cudaGetSymbolAddress(&h2_p, g_h2);
    float* xg = (float*)xg_p;
    float* h1 = (float*)h1_p;
    float* h2 = (float*)h2_p;

    cudaFuncSetAttribute(lstm_rec, cudaFuncAttributeMaxDynamicSharedMemorySize, REC_SMEM);

    dim3 ggrid(GG / 64, (TT * BB) / 64);   // (32, 2048)

    // Layer 1
    gemm_xg<<<ggrid, 256>>>(x, Wih1, bih1, bhh1, xg, 256);
    lstm_rec<<<NCTA, 256, REC_SMEM>>>(xg, Whh1, h1);
    // Layer 2 (XG buffer reused)
    gemm_xg<<<ggrid, 256>>>(h1, Wih2, bih2, bhh2, xg, 512);
    lstm_rec<<<NCTA, 256, REC_SMEM>>>(xg, Whh2, h2);
    // Head
    out_proj<<<(TT * BB * 32 + 255) / 256, 256>>>(h2, Wout, bout, out);
}

// round 8
// speedup vs baseline: 1.9453x; 1.5543x over previous
#include <cuda_runtime.h>
#include <cuda_bf16.h>
#include <math.h>
#include <stdint.h>

#define TT 2048
#define BB 64
#define HH 512
#define GG 2048

typedef unsigned long long u64;

// Scratch (module-load allocated).
__device__ float g_xg[268435456];                    // [T][B][4H] f32 (reused per layer)
__device__ float g_h1[67108864];                     // [T][B][H]
__device__ float g_h2[67108864];
__device__ __align__(16) __nv_bfloat16 g_wb[2][64][32][512];      // [split][jgrp][row][k]
__device__ __align__(16) __nv_bfloat16 g_hb[2][2][2][32][512];    // [split][par][bh][b][j]
__device__ unsigned g_grp[16 * 64];
__device__ unsigned g_root;
__device__ volatile unsigned g_gen;

__device__ __forceinline__ float sigm(float x) { return 1.0f / (1.0f + expf(-x)); }

__device__ __forceinline__ u64 ffma2(u64 a, u64 b, u64 c) {
    u64 d;
    asm("fma.rn.f32x2 %0, %1, %2, %3;" : "=l"(d) : "l"(a), "l"(b), "l"(c));
    return d;
}
__device__ __forceinline__ float f2_sum(u64 v) {
    return __uint_as_float((unsigned)v) + __uint_as_float((unsigned)(v >> 32));
}
__device__ __forceinline__ uint32_t smem_u32(const void* p) {
    uint32_t a;
    asm("{ .reg .u64 t; cvta.to.shared.u64 t, %1; cvt.u32.u64 %0, t; }" : "=r"(a) : "l"(p));
    return a;
}

#define LDSM_X4(r0, r1, r2, r3, addr) \
    asm volatile("ldmatrix.sync.aligned.m8n8.x4.shared.b16 {%0,%1,%2,%3}, [%4];" \
        : "=r"(r0), "=r"(r1), "=r"(r2), "=r"(r3) : "r"(addr))
#define LDSM_X2(r0, r1, addr) \
    asm volatile("ldmatrix.sync.aligned.m8n8.x2.shared.b16 {%0,%1}, [%2];" \
        : "=r"(r0), "=r"(r1) : "r"(addr))
#define MMA_BF16(d0, d1, d2, d3, a0, a1, a2, a3, b0, b1) \
    asm volatile("mma.sync.aligned.m16n8k16.row.col.f32.bf16.bf16.f32 " \
        "{%0,%1,%2,%3}, {%4,%5,%6,%7}, {%8,%9}, {%0,%1,%2,%3};" \
        : "+f"(d0), "+f"(d1), "+f"(d2), "+f"(d3) \
        : "r"(a0), "r"(a1), "r"(a2), "r"(a3), "r"(b0), "r"(b1))

// ---------------------------------------------------------------------------
// GEMM: C[M x 2048] = A[M x K]*B[2048 x K]^T + bi + bh  (FFMA2, unchanged R4)
// ---------------------------------------------------------------------------
#define GP 65

__global__ __launch_bounds__(256) void gemm_xg(
    const float* __restrict__ A, const float* __restrict__ B,
    const float* __restrict__ bi, const float* __restrict__ bh,
    float* __restrict__ C, int K)
{
    __shared__ u64 sA[16 * GP];
    __shared__ u64 sB[16 * GP];
    float2* sA2 = (float2*)sA;
    float2* sB2 = (float2*)sB;

    const int tid = threadIdx.x;
    const int tx = tid & 15;
    const int ty = tid >> 4;
    const int m0 = blockIdx.y * 64;
    const int n0 = blockIdx.x * 64;
    const int r0 = tid >> 3;
    const int kq = tid & 7;

    u64 acc[4][4];
    #pragma unroll
    for (int i = 0; i < 4; i++)
        #pragma unroll
        for (int j = 0; j < 4; j++) acc[i][j] = 0ULL;

    for (int kb = 0; kb < K; kb += 32) {
        #pragma unroll
        for (int half = 0; half < 2; half++) {
            int r = r0 + half * 32;
            float4 av = __ldg((const float4*)&A[(size_t)(m0 + r) * K + kb + kq * 4]);
            float4 bv = __ldg((const float4*)&B[(size_t)(n0 + r) * K + kb + kq * 4]);
            sA2[(2*kq+0) * GP + r] = make_float2(av.x, av.y);
            sA2[(2*kq+1) * GP + r] = make_float2(av.z, av.w);
            sB2[(2*kq+0) * GP + r] = make_float2(bv.x, bv.y);
            sB2[(2*kq+1) * GP + r] = make_float2(bv.z, bv.w);
        }
        __syncthreads();
        #pragma unroll
        for (int k2 = 0; k2 < 16; k2++) {
            u64 a0 = sA[k2 * GP + ty];
            u64 a1 = sA[k2 * GP + ty + 16];
            u64 a2 = sA[k2 * GP + ty + 32];
            u64 a3 = sA[k2 * GP + ty + 48];
            u64 b0 = sB[k2 * GP + tx];
            u64 b1 = sB[k2 * GP + tx + 16];
            u64 b2 = sB[k2 * GP + tx + 32];
            u64 b3 = sB[k2 * GP + tx + 48];
            acc[0][0] = ffma2(a0, b0, acc[0][0]); acc[0][1] = ffma2(a0, b1, acc[0][1]);
            acc[0][2] = ffma2(a0, b2, acc[0][2]); acc[0][3] = ffma2(a0, b3, acc[0][3]);
            acc[1][0] = ffma2(a1, b0, acc[1][0]); acc[1][1] = ffma2(a1, b1, acc[1][1]);
            acc[1][2] = ffma2(a1, b2, acc[1][2]); acc[1][3] = ffma2(a1, b3, acc[1][3]);
            acc[2][0] = ffma2(a2, b0, acc[2][0]); acc[2][1] = ffma2(a2, b1, acc[2][1]);
            acc[2][2] = ffma2(a2, b2, acc[2][2]); acc[2][3] = ffma2(a2, b3, acc[2][3]);
            acc[3][0] = ffma2(a3, b0, acc[3][0]); acc[3][1] = ffma2(a3, b1, acc[3][1]);
            acc[3][2] = ffma2(a3, b2, acc[3][2]); acc[3][3] = ffma2(a3, b3, acc[3][3]);
        }
        __syncthreads();
    }

    float bias[4];
    #pragma unroll
    for (int j = 0; j < 4; j++) {
        int n = n0 + tx + 16 * j;
        bias[j] = __ldg(&bi[n]) + __ldg(&bh[n]);
    }
    #pragma unroll
    for (int i = 0; i < 4; i++) {
        int m = m0 + ty + 16 * i;
        #pragma unroll
        for (int j = 0; j < 4; j++) {
            int n = n0 + tx + 16 * j;
            C[(size_t)m * GG + n] = f2_sum(acc[i][j]) + bias[j];
        }
    }
}

// ---------------------------------------------------------------------------
// prep_w: split Whh into bf16 hi/lo with gate-interleaved row ordering.
// Tile (jgrp): 32 rows, row r -> unit u=r>>2, gate g=r&3: W row g*512+jgrp*8+u.
// ---------------------------------------------------------------------------
__global__ __launch_bounds__(256) void prep_w(const float* __restrict__ Whh)
{
    int idx  = blockIdx.x * 256 + threadIdx.x;     // < 524288
    int jgrp = idx >> 13;                          // 0..63
    int r    = (idx >> 8) & 31;
    int k    = (idx & 255) * 2;
    int wrow = (r & 3) * 512 + jgrp * 8 + (r >> 2);

    float v0 = __ldg(&Whh[(size_t)wrow * HH + k]);
    float v1 = __ldg(&Whh[(size_t)wrow * HH + k + 1]);
    __nv_bfloat16 h0 = __float2bfloat16(v0);
    __nv_bfloat16 h1 = __float2bfloat16(v1);
    g_wb[0][jgrp][r][k]     = h0;
    g_wb[0][jgrp][r][k + 1] = h1;
    g_wb[1][jgrp][r][k]     = __float2bfloat16(v0 - __bfloat162float(h0));
    g_wb[1][jgrp][r][k + 1] = __float2bfloat16(v1 - __bfloat162float(h1));
}

// ---------------------------------------------------------------------------
// Persistent warp-MMA recurrence. 128 CTAs: jgrp(64) x bh(2), 256 threads.
// Per step: gates[32 rows, 32 b] = 3-split bf16 mma.sync over K=512.
// SMEM: W hi/lo [32][520]x2, h hi/lo [32][520]x2, D [32][33].
// ---------------------------------------------------------------------------
#define NCTA 128
#define PITCH 520                      // bf16 row pitch (1040 B; banks spread by 4)
#define WBLK (32 * PITCH * 2)          // 33280 B per split block
#define OFF_W 0
#define OFF_H (2 * WBLK)               // 66560
#define OFF_D (4 * WBLK)               // 133120
#define REC_SMEM (OFF_D + 32 * 33 * 4) // 137344 B

__device__ __forceinline__ void grid_bar()
{
    __threadfence();
    __syncthreads();
    if (threadIdx.x == 0) {
        unsigned gen = g_gen;
        unsigned grp = blockIdx.x >> 3;                 // 16 groups of 8
        if (atomicAdd(&g_grp[grp * 64], 1u) == 7u) {
            atomicExch(&g_grp[grp * 64], 0u);
            if (atomicAdd(&g_root, 1u) == 15u) {
                atomicExch(&g_root, 0u);
                __threadfence();
                g_gen = gen + 1u;
            }
        }
        while (g_gen == gen) { }
    }
    __syncthreads();
}

__global__ __launch_bounds__(256, 1) void lstm_rec(
    const float* __restrict__ xg, float* __restrict__ H)
{
    extern __shared__ char smc[];
    const uint32_t smb = smem_u32(smc);
    float* sD = (float*)(smc + OFF_D);

    const int tid  = threadIdx.x;
    const int wid  = tid >> 5;
    const int lane = tid & 31;
    const int jgrp = blockIdx.x >> 1;
    const int bh   = blockIdx.x & 1;
    const int j0   = jgrp * 8;

    // Load resident W tiles (hi + lo), padded rows.
    {
        uint4* dst = (uint4*)smc;                           // pitch 65 uint4
        #pragma unroll 2
        for (int s = 0; s < 2; s++) {
            const uint4* src = (const uint4*)&g_wb[s][jgrp][0][0];
            uint4* d = dst + s * (WBLK / 16);
            for (int i = tid; i < 2048; i += 256) {
                int row = i >> 6, c = i & 63;
                d[row * 65 + c] = __ldg(src + i);
            }
        }
    }

    // ldmatrix lane addressing.
    const int arow = lane & 15;                   // A: row within 16
    const uint32_t akoff = (lane >> 4) * 16;      // 0 or 16 bytes
    const int brow = lane & 7;                    // B: batch row
    const uint32_t bkoff = ((lane >> 3) & 1) * 16;
    const int m0 = (wid & 1) * 16;
    const int n0 = (wid >> 1) * 8;

    const uint32_t aHi0 = smb + OFF_W + (uint32_t)(m0 + arow) * (PITCH * 2) + akoff;
    const uint32_t aLo0 = aHi0 + WBLK;
    const uint32_t bHi0 = smb + OFF_H + (uint32_t)(n0 + brow) * (PITCH * 2) + bkoff;
    const uint32_t bLo0 = bHi0 + WBLK;

    // Pointwise mapping: exactly 256 threads = 8 units x 32 batches.
    const int u  = tid & 7;
    const int b  = tid >> 3;
    const int gb = bh * 32 + b;                   // global batch
    float c = 0.0f;

    for (int t = 0; t < TT; t++) {
        // xg prefetch (includes both biases from gemm_xg).
        float xv0 = __ldg(&xg[((size_t)t * BB + gb) * GG +        j0 + u]);
        float xv1 = __ldg(&xg[((size_t)t * BB + gb) * GG +  512 + j0 + u]);
        float xv2 = __ldg(&xg[((size_t)t * BB + gb) * GG + 1024 + j0 + u]);
        float xv3 = __ldg(&xg[((size_t)t * BB + gb) * GG + 1536 + j0 + u]);

        if (t > 0) {
            // Stage h(t-1) bf16 hi/lo image for our batch-half.
            int par = (t - 1) & 1;
            uint4* dst = (uint4*)(smc + OFF_H);
            #pragma unroll 2
            for (int s = 0; s < 2; s++) {
                const uint4* src = (const uint4*)&g_hb[s][par][bh][0][0];
                uint4* d = dst + s * (WBLK / 16);
                for (int i = tid; i < 2048; i += 256) {
                    int row = i >> 6, cc = i & 63;
                    d[row * 65 + cc] = __ldcg(src + i);
                }
            }
            __syncthreads();

            float d0 = 0.f, d1 = 0.f, d2 = 0.f, d3 = 0.f;
            #pragma unroll 8
            for (int ks = 0; ks < 32; ks++) {
                uint32_t ko = ks * 32;            // 16 bf16 per kstep
                uint32_t ah0, ah1, ah2, ah3, al0, al1, al2, al3;
                uint32_t bhr0, bhr1, blr0, blr1;
                LDSM_X4(ah0, ah1, ah2, ah3, aHi0 + ko);
                LDSM_X4(al0, al1, al2, al3, aLo0 + ko);
                LDSM_X2(bhr0, bhr1, bHi0 + ko);
                LDSM_X2(blr0, blr1, bLo0 + ko);
                MMA_BF16(d0, d1, d2, d3, ah0, ah1, ah2, ah3, bhr0, bhr1);
                MMA_BF16(d0, d1, d2, d3, ah0, ah1, ah2, ah3, blr0, blr1);
                MMA_BF16(d0, d1, d2, d3, al0, al1, al2, al3, bhr0, bhr1);
            }
            // Dump accumulators to SMEM for the pointwise remap.
            {
                int gid = lane >> 2, tig = lane & 3;
                int row = m0 + gid, col = n0 + tig * 2;
                sD[row * 33 + col]       = d0;
                sD[row * 33 + col + 1]   = d1;
                sD[(row + 8) * 33 + col]     = d2;
                sD[(row + 8) * 33 + col + 1] = d3;
            }
            __syncthreads();
        }

        // Fused pointwise: gates of unit u, batch b. Tile row = u*4+g.
        {
            float p0 = xv0, p1 = xv1, p2 = xv2, p3 = xv3;
            if (t > 0) {
                p0 += sD[(u * 4 + 0) * 33 + b];
                p1 += sD[(u * 4 + 1) * 33 + b];
                p2 += sD[(u * 4 + 2) * 33 + b];
                p3 += sD[(u * 4 + 3) * 33 + b];
            }
            float gi = sigm(p0);
            float gf = sigm(p1);
            float gz = tanhf(p2);
            float go = sigm(p3);
            c = gf * c + gi * gz;
            float hv = go * tanhf(c);

            H[((size_t)t * BB + gb) * HH + j0 + u] = hv;

            __nv_bfloat16 hi = __float2bfloat16(hv);
            __nv_bfloat16 lo = __float2bfloat16(hv - __bfloat162float(hi));
            int par = t & 1;
            g_hb[0][par][bh][b][j0 + u] = hi;
            g_hb[1][par][bh][b][j0 + u] = lo;
        }

        grid_bar();
    }
}

// ---------------------------------------------------------------------------
// Output head.
// ---------------------------------------------------------------------------
__global__ __launch_bounds__(256) void out_proj(
    const float* __restrict__ H2, const float* __restrict__ Wout,
    const float* __restrict__ bout, float* __restrict__ out)
{
    int w = (blockIdx.x * blockDim.x + threadIdx.x) >> 5;
    int lane = threadIdx.x & 31;
    if (w >= TT * BB) return;
    const float4* h  = (const float4*)(H2 + (size_t)w * HH);
    const float4* wv = (const float4*)Wout;
    float acc = 0.0f;
    #pragma unroll
    for (int i = lane; i < 128; i += 32) {
        float4 a = __ldg(h + i);
        float4 bb = __ldg(wv + i);
        acc += a.x*bb.x + a.y*bb.y + a.z*bb.z + a.w*bb.w;
    }
    #pragma unroll
    for (int off = 16; off; off >>= 1) acc += __shfl_xor_sync(0xffffffffu, acc, off);
    if (lane == 0) out[w] = 1.0f / (1.0f + expf(-(acc + __ldg(bout))));
}

// ---------------------------------------------------------------------------
extern "C" void kernel_launch(void* const* d_in, const int* in_sizes, int n_in,
                              void* d_out, int out_size)
{
    const float* x     = (const float*)d_in[0];
    const float* Wih1  = (const float*)d_in[1];
    const float* Whh1  = (const float*)d_in[2];
    const float* bih1  = (const float*)d_in[3];
    const float* bhh1  = (const float*)d_in[4];
    const float* Wih2  = (const float*)d_in[5];
    const float* Whh2  = (const float*)d_in[6];
    const float* bih2  = (const float*)d_in[7];
    const float* bhh2  = (const float*)d_in[8];
    const float* Wout  = (const float*)d_in[9];
    const float* bout  = (const float*)d_in[10];
    float* out = (float*)d_out;

    void *xg_p, *h1_p, *h2_p;
    cudaGetSymbolAddress(&xg_p, g_xg);
    cudaGetSymbolAddress(&h1_p, g_h1);
    cudaGetSymbolAddress(&h2_p, g_h2);
    float* xg = (float*)xg_p;
    float* h1 = (float*)h1_p;
    float* h2 = (float*)h2_p;

    cudaFuncSetAttribute(lstm_rec, cudaFuncAttributeMaxDynamicSharedMemorySize, REC_SMEM);

    dim3 ggrid(GG / 64, (TT * BB) / 64);

    // Layer 1
    gemm_xg<<<ggrid, 256>>>(x, Wih1, bih1, bhh1, xg, 256);
    prep_w<<<2048, 256>>>(Whh1);
    lstm_rec<<<NCTA, 256, REC_SMEM>>>(xg, h1);
    // Layer 2 (xg reused)
    gemm_xg<<<ggrid, 256>>>(h1, Wih2, bih2, bhh2, xg, 512);
    prep_w<<<2048, 256>>>(Whh2);
    lstm_rec<<<NCTA, 256, REC_SMEM>>>(xg, h2);
    // Head
    out_proj<<<(TT * BB * 32 + 255) / 256, 256>>>(h2, Wout, bout, out);
}

// round 9
// speedup vs baseline: 2.3162x; 1.1907x over previous
#include <cuda_runtime.h>
#include <cuda_bf16.h>
#include <math.h>
#include <stdint.h>

#define TT 2048
#define BB 64
#define HH 512
#define GG 2048

typedef unsigned long long u64;

// Scratch (module-load allocated).
__device__ float g_xg[268435456];                    // [T][B][4H] f32 (reused per layer)
__device__ float g_h1[67108864];                     // [T][B][H]
__device__ float g_h2[67108864];
__device__ __align__(16) __nv_bfloat16 g_ah[67108864];  // A image hi (x-split / h1-split)
__device__ __align__(16) __nv_bfloat16 g_al[67108864];  // A image lo
__device__ __align__(16) __nv_bfloat16 g_wih_h[1048576]; // W_ih hi [2048][512]
__device__ __align__(16) __nv_bfloat16 g_wih_l[1048576];
__device__ __align__(16) __nv_bfloat16 g_wb[2][64][32][512];      // [split][jgrp][row][k]
__device__ __align__(16) __nv_bfloat16 g_hb[2][2][2][32][512];    // [split][par][bh][b][j]
__device__ unsigned g_grp[16 * 64];
__device__ unsigned g_root;
__device__ volatile unsigned g_gen;

__device__ __forceinline__ float sigm(float x) { return 1.0f / (1.0f + expf(-x)); }

__device__ __forceinline__ uint32_t smem_u32(const void* p) {
    uint32_t a;
    asm("{ .reg .u64 t; cvta.to.shared.u64 t, %1; cvt.u32.u64 %0, t; }" : "=r"(a) : "l"(p));
    return a;
}

#define LDSM_X4(r0, r1, r2, r3, addr) \
    asm volatile("ldmatrix.sync.aligned.m8n8.x4.shared.b16 {%0,%1,%2,%3}, [%4];" \
        : "=r"(r0), "=r"(r1), "=r"(r2), "=r"(r3) : "r"(addr))
#define LDSM_X2(r0, r1, addr) \
    asm volatile("ldmatrix.sync.aligned.m8n8.x2.shared.b16 {%0,%1}, [%2];" \
        : "=r"(r0), "=r"(r1) : "r"(addr))
#define MMA_BF16(d0, d1, d2, d3, a0, a1, a2, a3, b0, b1) \
    asm volatile("mma.sync.aligned.m16n8k16.row.col.f32.bf16.bf16.f32 " \
        "{%0,%1,%2,%3}, {%4,%5,%6,%7}, {%8,%9}, {%0,%1,%2,%3};" \
        : "+f"(d0), "+f"(d1), "+f"(d2), "+f"(d3) \
        : "r"(a0), "r"(a1), "r"(a2), "r"(a3), "r"(b0), "r"(b1))
#define CP16(dst, src) \
    asm volatile("cp.async.cg.shared.global [%0], [%1], 16;" :: "r"(dst), "l"(src))

// ---------------------------------------------------------------------------
// prep_a: split f32 array into bf16 hi/lo images (for layer-1 input x).
// ---------------------------------------------------------------------------
__global__ __launch_bounds__(256) void prep_a(const float* __restrict__ src, int total)
{
    int idx = blockIdx.x * 256 + threadIdx.x;
    if (idx >= total) return;
    float v = src[idx];
    __nv_bfloat16 h = __float2bfloat16(v);
    g_ah[idx] = h;
    g_al[idx] = __float2bfloat16(v - __bfloat162float(h));
}

// ---------------------------------------------------------------------------
// prep_wih: split W_ih [2048][K] f32 into bf16 hi/lo at fixed pitch 512.
// ---------------------------------------------------------------------------
__global__ __launch_bounds__(256) void prep_wih(const float* __restrict__ W, int K)
{
    int idx = blockIdx.x * 256 + threadIdx.x;      // over 2048*K
    int n = idx / K;
    int k = idx - n * K;
    float v = W[idx];
    __nv_bfloat16 h = __float2bfloat16(v);
    g_wih_h[n * 512 + k] = h;
    g_wih_l[n * 512 + k] = __float2bfloat16(v - __bfloat162float(h));
}

// ---------------------------------------------------------------------------
// gemm_mma: C[M x 2048] = A[M x K]*W[2048 x K]^T + bi + bh via 3-split bf16
// mma.sync. CTA tile 128x128, 8 warps (64x32), K-chunk 32, cp.async 2-stage.
// A = g_ah/g_al (pitch K), B = g_wih_h/l (pitch 512).
// ---------------------------------------------------------------------------
#define KC 32
#define APB 80                      // row pitch bytes (40 bf16); conflict-free ldmatrix
#define REG (128 * APB)             // 10240 B per region
#define STG (4 * REG)               // Ah, Al, Bh, Bl
#define GSMEM (2 * STG)             // 81920 B

__global__ __launch_bounds__(256) void gemm_mma(
    const float* __restrict__ bi, const float* __restrict__ bh,
    float* __restrict__ C, int K)
{
    extern __shared__ __align__(16) char gsm[];
    const uint32_t smb = smem_u32(gsm);
    const int tid = threadIdx.x;
    const int wid = tid >> 5, lane = tid & 31;
    const int n0 = blockIdx.x * 128;
    const int m0 = blockIdx.y * 128;
    const int wm = (wid & 1) * 64;
    const int wn = (wid >> 1) * 32;

    auto load_chunk = [&](int c, int s) {
        int kb = c * KC;
        uint32_t base = smb + s * STG;
        #pragma unroll
        for (int j = 0; j < 8; j++) {
            int u = tid + j * 256;
            int r = u >> 9;                 // region 0..3
            int e = u & 511;
            int row = e >> 2, q = e & 3;
            const __nv_bfloat16* src;
            if (r == 0)      src = g_ah + (size_t)(m0 + row) * K + kb + q * 8;
            else if (r == 1) src = g_al + (size_t)(m0 + row) * K + kb + q * 8;
            else if (r == 2) src = g_wih_h + (size_t)(n0 + row) * 512 + kb + q * 8;
            else             src = g_wih_l + (size_t)(n0 + row) * 512 + kb + q * 8;
            CP16(base + r * REG + row * APB + q * 16, src);
        }
        asm volatile("cp.async.commit_group;");
    };

    float acc[4][4][4];
    #pragma unroll
    for (int a = 0; a < 4; a++)
        #pragma unroll
        for (int b = 0; b < 4; b++)
            #pragma unroll
            for (int cix = 0; cix < 4; cix++) acc[a][b][cix] = 0.0f;

    const int NC = K / KC;
    load_chunk(0, 0);
    for (int c = 0; c < NC; c++) {
        if (c + 1 < NC) {
            load_chunk(c + 1, (c + 1) & 1);
            asm volatile("cp.async.wait_group 1;");
        } else {
            asm volatile("cp.async.wait_group 0;");
        }
        __syncthreads();
        uint32_t st = smb + (c & 1) * STG;
        #pragma unroll
        for (int ks = 0; ks < 2; ks++) {
            uint32_t ko = ks * 32;
            uint32_t Ah[4][4], Al[4][4], Bh[4][2], Bl[4][2];
            #pragma unroll
            for (int f = 0; f < 4; f++) {
                uint32_t ar = st + (uint32_t)(wm + f * 16 + (lane & 15)) * APB
                            + ((lane >> 4) * 16) + ko;
                LDSM_X4(Ah[f][0], Ah[f][1], Ah[f][2], Ah[f][3], ar);
                LDSM_X4(Al[f][0], Al[f][1], Al[f][2], Al[f][3], ar + REG);
                uint32_t br = st + 2 * REG + (uint32_t)(wn + f * 8 + (lane & 7)) * APB
                            + (((lane >> 3) & 1) * 16) + ko;
                LDSM_X2(Bh[f][0], Bh[f][1], br);
                LDSM_X2(Bl[f][0], Bl[f][1], br + REG);
            }
            #pragma unroll
            for (int mf = 0; mf < 4; mf++)
                #pragma unroll
                for (int nf = 0; nf < 4; nf++) {
                    MMA_BF16(acc[mf][nf][0], acc[mf][nf][1], acc[mf][nf][2], acc[mf][nf][3],
                             Ah[mf][0], Ah[mf][1], Ah[mf][2], Ah[mf][3], Bh[nf][0], Bh[nf][1]);
                    MMA_BF16(acc[mf][nf][0], acc[mf][nf][1], acc[mf][nf][2], acc[mf][nf][3],
                             Ah[mf][0], Ah[mf][1], Ah[mf][2], Ah[mf][3], Bl[nf][0], Bl[nf][1]);
                    MMA_BF16(acc[mf][nf][0], acc[mf][nf][1], acc[mf][nf][2], acc[mf][nf][3],
                             Al[mf][0], Al[mf][1], Al[mf][2], Al[mf][3], Bh[nf][0], Bh[nf][1]);
                }
        }
        __syncthreads();
    }

    #pragma unroll
    for (int nf = 0; nf < 4; nf++) {
        int n = n0 + wn + nf * 8 + (lane & 3) * 2;
        float b0 = __ldg(&bi[n]) + __ldg(&bh[n]);
        float b1 = __ldg(&bi[n + 1]) + __ldg(&bh[n + 1]);
        #pragma unroll
        for (int mf = 0; mf < 4; mf++) {
            int m = m0 + wm + mf * 16 + (lane >> 2);
            *(float2*)&C[(size_t)m * GG + n] =
                make_float2(acc[mf][nf][0] + b0, acc[mf][nf][1] + b1);
            *(float2*)&C[(size_t)(m + 8) * GG + n] =
                make_float2(acc[mf][nf][2] + b0, acc[mf][nf][3] + b1);
        }
    }
}

// ---------------------------------------------------------------------------
// prep_w: split Whh into bf16 hi/lo with gate-interleaved row ordering.
// ---------------------------------------------------------------------------
__global__ __launch_bounds__(256) void prep_w(const float* __restrict__ Whh)
{
    int idx  = blockIdx.x * 256 + threadIdx.x;     // < 524288
    int jgrp = idx >> 13;
    int r    = (idx >> 8) & 31;
    int k    = (idx & 255) * 2;
    int wrow = (r & 3) * 512 + jgrp * 8 + (r >> 2);

    float v0 = __ldg(&Whh[(size_t)wrow * HH + k]);
    float v1 = __ldg(&Whh[(size_t)wrow * HH + k + 1]);
    __nv_bfloat16 h0 = __float2bfloat16(v0);
    __nv_bfloat16 h1 = __float2bfloat16(v1);
    g_wb[0][jgrp][r][k]     = h0;
    g_wb[0][jgrp][r][k + 1] = h1;
    g_wb[1][jgrp][r][k]     = __float2bfloat16(v0 - __bfloat162float(h0));
    g_wb[1][jgrp][r][k + 1] = __float2bfloat16(v1 - __bfloat162float(h1));
}

// ---------------------------------------------------------------------------
// Persistent warp-MMA recurrence (unchanged R8, plus persistent A-image store).
// ---------------------------------------------------------------------------
#define NCTA 128
#define PITCH 520
#define WBLK (32 * PITCH * 2)
#define OFF_W 0
#define OFF_H (2 * WBLK)
#define OFF_D (4 * WBLK)
#define REC_SMEM (OFF_D + 32 * 33 * 4)

__device__ __forceinline__ void grid_bar()
{
    __threadfence();
    __syncthreads();
    if (threadIdx.x == 0) {
        unsigned gen = g_gen;
        unsigned grp = blockIdx.x >> 3;
        if (atomicAdd(&g_grp[grp * 64], 1u) == 7u) {
            atomicExch(&g_grp[grp * 64], 0u);
            if (atomicAdd(&g_root, 1u) == 15u) {
                atomicExch(&g_root, 0u);
                __threadfence();
                g_gen = gen + 1u;
            }
        }
        while (g_gen == gen) { }
    }
    __syncthreads();
}

__global__ __launch_bounds__(256, 1) void lstm_rec(
    const float* __restrict__ xg, float* __restrict__ H)
{
    extern __shared__ char smc[];
    const uint32_t smb = smem_u32(smc);
    float* sD = (float*)(smc + OFF_D);

    const int tid  = threadIdx.x;
    const int wid  = tid >> 5;
    const int lane = tid & 31;
    const int jgrp = blockIdx.x >> 1;
    const int bh   = blockIdx.x & 1;
    const int j0   = jgrp * 8;

    {
        uint4* dst = (uint4*)smc;
        #pragma unroll 2
        for (int s = 0; s < 2; s++) {
            const uint4* src = (const uint4*)&g_wb[s][jgrp][0][0];
            uint4* d = dst + s * (WBLK / 16);
            for (int i = tid; i < 2048; i += 256) {
                int row = i >> 6, c = i & 63;
                d[row * 65 + c] = __ldg(src + i);
            }
        }
    }

    const int arow = lane & 15;
    const uint32_t akoff = (lane >> 4) * 16;
    const int brow = lane & 7;
    const uint32_t bkoff = ((lane >> 3) & 1) * 16;
    const int m0 = (wid & 1) * 16;
    const int n0 = (wid >> 1) * 8;

    const uint32_t aHi0 = smb + OFF_W + (uint32_t)(m0 + arow) * (PITCH * 2) + akoff;
    const uint32_t aLo0 = aHi0 + WBLK;
    const uint32_t bHi0 = smb + OFF_H + (uint32_t)(n0 + brow) * (PITCH * 2) + bkoff;
    const uint32_t bLo0 = bHi0 + WBLK;

    const int u  = tid & 7;
    const int b  = tid >> 3;
    const int gb = bh * 32 + b;
    float c = 0.0f;

    for (int t = 0; t < TT; t++) {
        float xv0 = __ldg(&xg[((size_t)t * BB + gb) * GG +        j0 + u]);
        float xv1 = __ldg(&xg[((size_t)t * BB + gb) * GG +  512 + j0 + u]);
        float xv2 = __ldg(&xg[((size_t)t * BB + gb) * GG + 1024 + j0 + u]);
        float xv3 = __ldg(&xg[((size_t)t * BB + gb) * GG + 1536 + j0 + u]);

        if (t > 0) {
            int par = (t - 1) & 1;
            uint4* dst = (uint4*)(smc + OFF_H);
            #pragma unroll 2
            for (int s = 0; s < 2; s++) {
                const uint4* src = (const uint4*)&g_hb[s][par][bh][0][0];
                uint4* d = dst + s * (WBLK / 16);
                for (int i = tid; i < 2048; i += 256) {
                    int row = i >> 6, cc = i & 63;
                    d[row * 65 + cc] = __ldcg(src + i);
                }
            }
            __syncthreads();

            float d0 = 0.f, d1 = 0.f, d2 = 0.f, d3 = 0.f;
            #pragma unroll 8
            for (int ks = 0; ks < 32; ks++) {
                uint32_t ko = ks * 32;
                uint32_t ah0, ah1, ah2, ah3, al0, al1, al2, al3;
                uint32_t bhr0, bhr1, blr0, blr1;
                LDSM_X4(ah0, ah1, ah2, ah3, aHi0 + ko);
                LDSM_X4(al0, al1, al2, al3, aLo0 + ko);
                LDSM_X2(bhr0, bhr1, bHi0 + ko);
                LDSM_X2(blr0, blr1, bLo0 + ko);
                MMA_BF16(d0, d1, d2, d3, ah0, ah1, ah2, ah3, bhr0, bhr1);
                MMA_BF16(d0, d1, d2, d3, ah0, ah1, ah2, ah3, blr0, blr1);
                MMA_BF16(d0, d1, d2, d3, al0, al1, al2, al3, bhr0, bhr1);
            }
            {
                int gid = lane >> 2, tig = lane & 3;
                int row = m0 + gid, col = n0 + tig * 2;
                sD[row * 33 + col]           = d0;
                sD[row * 33 + col + 1]       = d1;
                sD[(row + 8) * 33 + col]     = d2;
                sD[(row + 8) * 33 + col + 1] = d3;
            }
            __syncthreads();
        }

        {
            float p0 = xv0, p1 = xv1, p2 = xv2, p3 = xv3;
            if (t > 0) {
                p0 += sD[(u * 4 + 0) * 33 + b];
                p1 += sD[(u * 4 + 1) * 33 + b];
                p2 += sD[(u * 4 + 2) * 33 + b];
                p3 += sD[(u * 4 + 3) * 33 + b];
            }
            float gi = sigm(p0);
            float gf = sigm(p1);
            float gz = tanhf(p2);
            float go = sigm(p3);
            c = gf * c + gi * gz;
            float hv = go * tanhf(c);

            H[((size_t)t * BB + gb) * HH + j0 + u] = hv;

            __nv_bfloat16 hi = __float2bfloat16(hv);
            __nv_bfloat16 lo = __float2bfloat16(hv - __bfloat162float(hi));
            int par = t & 1;
            g_hb[0][par][bh][b][j0 + u] = hi;
            g_hb[1][par][bh][b][j0 + u] = lo;
            // Persistent A image for the next layer's tensor-core GEMM.
            size_t aidx = ((size_t)t * BB + gb) * HH + j0 + u;
            g_ah[aidx] = hi;
            g_al[aidx] = lo;
        }

        grid_bar();
    }
}

// ---------------------------------------------------------------------------
// Output head.
// ---------------------------------------------------------------------------
__global__ __launch_bounds__(256) void out_proj(
    const float* __restrict__ H2, const float* __restrict__ Wout,
    const float* __restrict__ bout, float* __restrict__ out)
{
    int w = (blockIdx.x * blockDim.x + threadIdx.x) >> 5;
    int lane = threadIdx.x & 31;
    if (w >= TT * BB) return;
    const float4* h  = (const float4*)(H2 + (size_t)w * HH);
    const float4* wv = (const float4*)Wout;
    float acc = 0.0f;
    #pragma unroll
    for (int i = lane; i < 128; i += 32) {
        float4 a = __ldg(h + i);
        float4 bb = __ldg(wv + i);
        acc += a.x*bb.x + a.y*bb.y + a.z*bb.z + a.w*bb.w;
    }
    #pragma unroll
    for (int off = 16; off; off >>= 1) acc += __shfl_xor_sync(0xffffffffu, acc, off);
    if (lane == 0) out[w] = 1.0f / (1.0f + expf(-(acc + __ldg(bout))));
}

// ---------------------------------------------------------------------------
extern "C" void kernel_launch(void* const* d_in, const int* in_sizes, int n_in,
                              void* d_out, int out_size)
{
    const float* x     = (const float*)d_in[0];
    const float* Wih1  = (const float*)d_in[1];
    const float* Whh1  = (const float*)d_in[2];
    const float* bih1  = (const float*)d_in[3];
    const float* bhh1  = (const float*)d_in[4];
    const float* Wih2  = (const float*)d_in[5];
    const float* Whh2  = (const float*)d_in[6];
    const float* bih2  = (const float*)d_in[7];
    const float* bhh2  = (const float*)d_in[8];
    const float* Wout  = (const float*)d_in[9];
    const float* bout  = (const float*)d_in[10];
    float* out = (float*)d_out;

    void *xg_p, *h1_p, *h2_p;
    cudaGetSymbolAddress(&xg_p, g_xg);
    cudaGetSymbolAddress(&h1_p, g_h1);
    cudaGetSymbolAddress(&h2_p, g_h2);
    float* xg = (float*)xg_p;
    float* h1 = (float*)h1_p;
    float* h2 = (float*)h2_p;

    cudaFuncSetAttribute(lstm_rec, cudaFuncAttributeMaxDynamicSharedMemorySize, REC_SMEM);
    cudaFuncSetAttribute(gemm_mma, cudaFuncAttributeMaxDynamicSharedMemorySize, GSMEM);

    dim3 ggrid(16, 1024);   // (N/128, M/128)

    // Layer 1
    prep_a<<<(TT * BB * 256) / 256 / 256 * 256 ? (TT * BB * 256 + 255) / 256 : 1, 256>>>(x, TT * BB * 256);
    prep_wih<<<(2048 * 256) / 256, 256>>>(Wih1, 256);
    gemm_mma<<<ggrid, 256, GSMEM>>>(bih1, bhh1, xg, 256);
    prep_w<<<2048, 256>>>(Whh1);
    lstm_rec<<<NCTA, 256, REC_SMEM>>>(xg, h1);      // also writes g_ah/g_al (layer-2 A)
    // Layer 2 (xg reused)
    prep_wih<<<(2048 * 512) / 256, 256>>>(Wih2, 512);
    gemm_mma<<<ggrid, 256, GSMEM>>>(bih2, bhh2, xg, 512);
    prep_w<<<2048, 256>>>(Whh2);
    lstm_rec<<<NCTA, 256, REC_SMEM>>>(xg, h2);
    // Head
    out_proj<<<(TT * BB * 32 + 255) / 256, 256>>>(h2, Wout, bout, out);
}

// round 10
// speedup vs baseline: 2.7712x; 1.1964x over previous
#include <cuda_runtime.h>
#include <cuda_bf16.h>
#include <math.h>
#include <stdint.h>

#define TT 2048
#define BB 64
#define HH 512
#define GG 2048

typedef unsigned long long u64;

// Scratch (module-load allocated).
__device__ float g_xg[268435456];                    // [T][B][4H] f32 (reused per layer)
__device__ float g_h1[67108864];                     // [T][B][H] (unused; kept for ABI)
__device__ float g_h2[67108864];
__device__ __align__(16) __nv_bfloat16 g_ah[67108864];  // A image hi (x-split / h1-split)
__device__ __align__(16) __nv_bfloat16 g_al[67108864];  // A image lo
__device__ __align__(16) __nv_bfloat16 g_wih_h[1048576]; // W_ih hi [2048][512]
__device__ __align__(16) __nv_bfloat16 g_wih_l[1048576];
__device__ __align__(16) __nv_bfloat16 g_wb[2][64][32][512];      // [split][jgrp][row][k]
__device__ __align__(16) __nv_bfloat16 g_hb[2][2][2][32][512];    // [split][par][bh][b][j]
__device__ unsigned g_gb[2][8 * 32];                 // subgroup counters (128B apart)
__device__ unsigned g_gr[2 * 32];                    // root counters
__device__ unsigned g_gg[2 * 32];                    // generations

__device__ __forceinline__ float sigm_f(float x) {
    return __fdividef(1.0f, 1.0f + __expf(-x));
}
__device__ __forceinline__ float tanh_f(float x) {
    float ax = fabsf(x);
    float e = __expf(-2.0f * ax);
    float r = __fdividef(1.0f - e, 1.0f + e);
    return copysignf(r, x);
}
__device__ __forceinline__ uint32_t smem_u32(const void* p) {
    uint32_t a;
    asm("{ .reg .u64 t; cvta.to.shared.u64 t, %1; cvt.u32.u64 %0, t; }" : "=r"(a) : "l"(p));
    return a;
}
__device__ __forceinline__ unsigned atom_add_acqrel(unsigned* p) {
    unsigned o;
    asm volatile("atom.acq_rel.gpu.global.add.u32 %0, [%1], %2;"
                 : "=r"(o) : "l"(p), "r"(1u) : "memory");
    return o;
}
__device__ __forceinline__ void st_release(unsigned* p, unsigned v) {
    asm volatile("st.release.gpu.global.u32 [%0], %1;" :: "l"(p), "r"(v) : "memory");
}
__device__ __forceinline__ unsigned ld_acquire(unsigned* p) {
    unsigned v;
    asm volatile("ld.acquire.gpu.global.u32 %0, [%1];" : "=r"(v) : "l"(p) : "memory");
    return v;
}

#define LDSM_X4(r0, r1, r2, r3, addr) \
    asm volatile("ldmatrix.sync.aligned.m8n8.x4.shared.b16 {%0,%1,%2,%3}, [%4];" \
        : "=r"(r0), "=r"(r1), "=r"(r2), "=r"(r3) : "r"(addr))
#define LDSM_X2(r0, r1, addr) \
    asm volatile("ldmatrix.sync.aligned.m8n8.x2.shared.b16 {%0,%1}, [%2];" \
        : "=r"(r0), "=r"(r1) : "r"(addr))
#define MMA_BF16(d0, d1, d2, d3, a0, a1, a2, a3, b0, b1) \
    asm volatile("mma.sync.aligned.m16n8k16.row.col.f32.bf16.bf16.f32 " \
        "{%0,%1,%2,%3}, {%4,%5,%6,%7}, {%8,%9}, {%0,%1,%2,%3};" \
        : "+f"(d0), "+f"(d1), "+f"(d2), "+f"(d3) \
        : "r"(a0), "r"(a1), "r"(a2), "r"(a3), "r"(b0), "r"(b1))
#define CP16(dst, src) \
    asm volatile("cp.async.cg.shared.global [%0], [%1], 16;" :: "r"(dst), "l"(src))

// ---------------------------------------------------------------------------
// prep_a: split f32 array into bf16 hi/lo images (for layer-1 input x).
// ---------------------------------------------------------------------------
__global__ __launch_bounds__(256) void prep_a(const float* __restrict__ src, int total)
{
    int idx = blockIdx.x * 256 + threadIdx.x;
    if (idx >= total) return;
    float v = src[idx];
    __nv_bfloat16 h = __float2bfloat16(v);
    g_ah[idx] = h;
    g_al[idx] = __float2bfloat16(v - __bfloat162float(h));
}

// ---------------------------------------------------------------------------
// prep_wih: split W_ih [2048][K] f32 into bf16 hi/lo at fixed pitch 512.
// ---------------------------------------------------------------------------
__global__ __launch_bounds__(256) void prep_wih(const float* __restrict__ W, int K)
{
    int idx = blockIdx.x * 256 + threadIdx.x;
    int n = idx / K;
    int k = idx - n * K;
    float v = W[idx];
    __nv_bfloat16 h = __float2bfloat16(v);
    g_wih_h[n * 512 + k] = h;
    g_wih_l[n * 512 + k] = __float2bfloat16(v - __bfloat162float(h));
}

// ---------------------------------------------------------------------------
// gemm_mma: C[M x 2048] = A[M x K]*W[2048 x K]^T + bi + bh (3-split bf16 mma).
// CTA tile 128x128, 8 warps (64x32), K-chunk 32, cp.async 2-stage. (R9)
// ---------------------------------------------------------------------------
#define KC 32
#define APB 80
#define REG (128 * APB)
#define STG (4 * REG)
#define GSMEM (2 * STG)

__global__ __launch_bounds__(256) void gemm_mma(
    const float* __restrict__ bi, const float* __restrict__ bh,
    float* __restrict__ C, int K)
{
    extern __shared__ __align__(16) char gsm[];
    const uint32_t smb = smem_u32(gsm);
    const int tid = threadIdx.x;
    const int wid = tid >> 5, lane = tid & 31;
    const int n0 = blockIdx.x * 128;
    const int m0 = blockIdx.y * 128;
    const int wm = (wid & 1) * 64;
    const int wn = (wid >> 1) * 32;

    auto load_chunk = [&](int c, int s) {
        int kb = c * KC;
        uint32_t base = smb + s * STG;
        #pragma unroll
        for (int j = 0; j < 8; j++) {
            int u = tid + j * 256;
            int r = u >> 9;
            int e = u & 511;
            int row = e >> 2, q = e & 3;
            const __nv_bfloat16* src;
            if (r == 0)      src = g_ah + (size_t)(m0 + row) * K + kb + q * 8;
            else if (r == 1) src = g_al + (size_t)(m0 + row) * K + kb + q * 8;
            else if (r == 2) src = g_wih_h + (size_t)(n0 + row) * 512 + kb + q * 8;
            else             src = g_wih_l + (size_t)(n0 + row) * 512 + kb + q * 8;
            CP16(base + r * REG + row * APB + q * 16, src);
        }
        asm volatile("cp.async.commit_group;");
    };

    float acc[4][4][4];
    #pragma unroll
    for (int a = 0; a < 4; a++)
        #pragma unroll
        for (int b = 0; b < 4; b++)
            #pragma unroll
            for (int cix = 0; cix < 4; cix++) acc[a][b][cix] = 0.0f;

    const int NC = K / KC;
    load_chunk(0, 0);
    for (int c = 0; c < NC; c++) {
        if (c + 1 < NC) {
            load_chunk(c + 1, (c + 1) & 1);
            asm volatile("cp.async.wait_group 1;");
        } else {
            asm volatile("cp.async.wait_group 0;");
        }
        __syncthreads();
        uint32_t st = smb + (c & 1) * STG;
        #pragma unroll
        for (int ks = 0; ks < 2; ks++) {
            uint32_t ko = ks * 32;
            uint32_t Ah[4][4], Al[4][4], Bh[4][2], Bl[4][2];
            #pragma unroll
            for (int f = 0; f < 4; f++) {
                uint32_t ar = st + (uint32_t)(wm + f * 16 + (lane & 15)) * APB
                            + ((lane >> 4) * 16) + ko;
                LDSM_X4(Ah[f][0], Ah[f][1], Ah[f][2], Ah[f][3], ar);
                LDSM_X4(Al[f][0], Al[f][1], Al[f][2], Al[f][3], ar + REG);
                uint32_t br = st + 2 * REG + (uint32_t)(wn + f * 8 + (lane & 7)) * APB
                            + (((lane >> 3) & 1) * 16) + ko;
                LDSM_X2(Bh[f][0], Bh[f][1], br);
                LDSM_X2(Bl[f][0], Bl[f][1], br + REG);
            }
            #pragma unroll
            for (int mf = 0; mf < 4; mf++)
                #pragma unroll
                for (int nf = 0; nf < 4; nf++) {
                    MMA_BF16(acc[mf][nf][0], acc[mf][nf][1], acc[mf][nf][2], acc[mf][nf][3],
                             Ah[mf][0], Ah[mf][1], Ah[mf][2], Ah[mf][3], Bh[nf][0], Bh[nf][1]);
                    MMA_BF16(acc[mf][nf][0], acc[mf][nf][1], acc[mf][nf][2], acc[mf][nf][3],
                             Ah[mf][0], Ah[mf][1], Ah[mf][2], Ah[mf][3], Bl[nf][0], Bl[nf][1]);
                    MMA_BF16(acc[mf][nf][0], acc[mf][nf][1], acc[mf][nf][2], acc[mf][nf][3],
                             Al[mf][0], Al[mf][1], Al[mf][2], Al[mf][3], Bh[nf][0], Bh[nf][1]);
                }
        }
        __syncthreads();
    }

    #pragma unroll
    for (int nf = 0; nf < 4; nf++) {
        int n = n0 + wn + nf * 8 + (lane & 3) * 2;
        float b0 = __ldg(&bi[n]) + __ldg(&bh[n]);
        float b1 = __ldg(&bi[n + 1]) + __ldg(&bh[n + 1]);
        #pragma unroll
        for (int mf = 0; mf < 4; mf++) {
            int m = m0 + wm + mf * 16 + (lane >> 2);
            *(float2*)&C[(size_t)m * GG + n] =
                make_float2(acc[mf][nf][0] + b0, acc[mf][nf][1] + b1);
            *(float2*)&C[(size_t)(m + 8) * GG + n] =
                make_float2(acc[mf][nf][2] + b0, acc[mf][nf][3] + b1);
        }
    }
}

// ---------------------------------------------------------------------------
// prep_w: split Whh into bf16 hi/lo with gate-interleaved row ordering.
// ---------------------------------------------------------------------------
__global__ __launch_bounds__(256) void prep_w(const float* __restrict__ Whh)
{
    int idx  = blockIdx.x * 256 + threadIdx.x;
    int jgrp = idx >> 13;
    int r    = (idx >> 8) & 31;
    int k    = (idx & 255) * 2;
    int wrow = (r & 3) * 512 + jgrp * 8 + (r >> 2);

    float v0 = __ldg(&Whh[(size_t)wrow * HH + k]);
    float v1 = __ldg(&Whh[(size_t)wrow * HH + k + 1]);
    __nv_bfloat16 h0 = __float2bfloat16(v0);
    __nv_bfloat16 h1 = __float2bfloat16(v1);
    g_wb[0][jgrp][r][k]     = h0;
    g_wb[0][jgrp][r][k + 1] = h1;
    g_wb[1][jgrp][r][k]     = __float2bfloat16(v0 - __bfloat162float(h0));
    g_wb[1][jgrp][r][k + 1] = __float2bfloat16(v1 - __bfloat162float(h1));
}

// ---------------------------------------------------------------------------
// Persistent warp-MMA recurrence. 128 CTAs: jgrp(64) x bh(2), 256 threads.
// Batch-half-scoped release/acquire barriers; cp.async chunked h staging
// overlapped with MMA; fast-math pointwise.
// ---------------------------------------------------------------------------
#define NCTA 128
#define PITCH 520
#define WBLK (32 * PITCH * 2)
#define OFF_W 0
#define OFF_H (2 * WBLK)
#define OFF_D (4 * WBLK)
#define REC_SMEM (OFF_D + 32 * 33 * 4)

__global__ __launch_bounds__(256, 1) void lstm_rec(
    const float* __restrict__ xg, float* __restrict__ H, int isL2)
{
    extern __shared__ char smc[];
    const uint32_t smb = smem_u32(smc);
    float* sD = (float*)(smc + OFF_D);

    const int tid  = threadIdx.x;
    const int wid  = tid >> 5;
    const int lane = tid & 31;
    const int jgrp = blockIdx.x >> 1;
    const int bh   = blockIdx.x & 1;
    const int j0   = jgrp * 8;
    const int sub  = jgrp >> 3;                   // 8 subgroups of 8 per bh

    // Resident W tiles (hi + lo), padded rows.
    {
        uint4* dst = (uint4*)smc;
        #pragma unroll 2
        for (int s = 0; s < 2; s++) {
            const uint4* src = (const uint4*)&g_wb[s][jgrp][0][0];
            uint4* d = dst + s * (WBLK / 16);
            for (int i = tid; i < 2048; i += 256) {
                int row = i >> 6, c = i & 63;
                d[row * 65 + c] = __ldg(src + i);
            }
        }
    }

    const int arow = lane & 15;
    const uint32_t akoff = (lane >> 4) * 16;
    const int brow = lane & 7;
    const uint32_t bkoff = ((lane >> 3) & 1) * 16;
    const int m0 = (wid & 1) * 16;
    const int n0 = (wid >> 1) * 8;

    const uint32_t aHi0 = smb + OFF_W + (uint32_t)(m0 + arow) * (PITCH * 2) + akoff;
    const uint32_t aLo0 = aHi0 + WBLK;
    const uint32_t bHi0 = smb + OFF_H + (uint32_t)(n0 + brow) * (PITCH * 2) + bkoff;
    const uint32_t bLo0 = bHi0 + WBLK;

    const int u  = tid & 7;
    const int b  = tid >> 3;
    const int gb = bh * 32 + b;
    float c = 0.0f;

    unsigned genv = g_gg[bh * 32];                // stable before first barrier

    for (int t = 0; t < TT; t++) {
        // Fire h(t-1) staging FIRST (4 cp.async chunk groups), overlap w/ MMA.
        if (t > 0) {
            int par = (t - 1) & 1;
            const __nv_bfloat16* baseH = &g_hb[0][par][bh][0][0];
            const __nv_bfloat16* baseL = &g_hb[1][par][bh][0][0];
            #pragma unroll
            for (int ck = 0; ck < 4; ck++) {
                #pragma unroll
                for (int j = 0; j < 2; j++) {
                    int i = tid * 2 + j;          // 0..511
                    int row = i >> 4, q = i & 15;
                    uint32_t dst = smb + OFF_H + (uint32_t)row * (PITCH * 2)
                                 + (uint32_t)(ck * 16 + q) * 16;
                    CP16(dst, baseH + row * 512 + ck * 128 + q * 8);
                    CP16(dst + WBLK, baseL + row * 512 + ck * 128 + q * 8);
                }
                asm volatile("cp.async.commit_group;");
            }
        }

        // xg prefetch (biases already folded in by gemm_mma).
        float xv0 = __ldg(&xg[((size_t)t * BB + gb) * GG +        j0 + u]);
        float xv1 = __ldg(&xg[((size_t)t * BB + gb) * GG +  512 + j0 + u]);
        float xv2 = __ldg(&xg[((size_t)t * BB + gb) * GG + 1024 + j0 + u]);
        float xv3 = __ldg(&xg[((size_t)t * BB + gb) * GG + 1536 + j0 + u]);

        if (t > 0) {
            float d0 = 0.f, d1 = 0.f, d2 = 0.f, d3 = 0.f;
            #pragma unroll
            for (int ck = 0; ck < 4; ck++) {
                if (ck == 0)      asm volatile("cp.async.wait_group 3;");
                else if (ck == 1) asm volatile("cp.async.wait_group 2;");
                else if (ck == 2) asm volatile("cp.async.wait_group 1;");
                else              asm volatile("cp.async.wait_group 0;");
                __syncthreads();
                #pragma unroll
                for (int ks = 0; ks < 8; ks++) {
                    uint32_t ko = (uint32_t)(ck * 8 + ks) * 32;
                    uint32_t ah0, ah1, ah2, ah3, al0, al1, al2, al3;
                    uint32_t bhr0, bhr1, blr0, blr1;
                    LDSM_X4(ah0, ah1, ah2, ah3, aHi0 + ko);
                    LDSM_X4(al0, al1, al2, al3, aLo0 + ko);
                    LDSM_X2(bhr0, bhr1, bHi0 + ko);
                    LDSM_X2(blr0, blr1, bLo0 + ko);
                    MMA_BF16(d0, d1, d2, d3, ah0, ah1, ah2, ah3, bhr0, bhr1);
                    MMA_BF16(d0, d1, d2, d3, ah0, ah1, ah2, ah3, blr0, blr1);
                    MMA_BF16(d0, d1, d2, d3, al0, al1, al2, al3, bhr0, bhr1);
                }
            }
            {
                int gid = lane >> 2, tig = lane & 3;
                int row = m0 + gid, col = n0 + tig * 2;
                sD[row * 33 + col]           = d0;
                sD[row * 33 + col + 1]       = d1;
                sD[(row + 8) * 33 + col]     = d2;
                sD[(row + 8) * 33 + col + 1] = d3;
            }
            __syncthreads();
        }

        // Fused pointwise: gates of unit u, batch b (tile row = u*4+g).
        {
            float p0 = xv0, p1 = xv1, p2 = xv2, p3 = xv3;
            if (t > 0) {
                p0 += sD[(u * 4 + 0) * 33 + b];
                p1 += sD[(u * 4 + 1) * 33 + b];
                p2 += sD[(u * 4 + 2) * 33 + b];
                p3 += sD[(u * 4 + 3) * 33 + b];
            }
            float gi = sigm_f(p0);
            float gf = sigm_f(p1);
            float gz = tanh_f(p2);
            float go = sigm_f(p3);
            c = gf * c + gi * gz;
            float hv = go * tanh_f(c);

            __nv_bfloat16 hi = __float2bfloat16(hv);
            __nv_bfloat16 lo = __float2bfloat16(hv - __bfloat162float(hi));
            int par = t & 1;
            g_hb[0][par][bh][b][j0 + u] = hi;
            g_hb[1][par][bh][b][j0 + u] = lo;
            if (isL2) {
                H[((size_t)t * BB + gb) * HH + j0 + u] = hv;   // out_proj input
            } else {
                size_t aidx = ((size_t)t * BB + gb) * HH + j0 + u;
                g_ah[aidx] = hi;                               // layer-2 GEMM A image
                g_al[aidx] = lo;
            }
        }

        // Batch-half-scoped two-level barrier (release/acquire; no membar).
        __syncthreads();
        genv += 1;
        if (tid == 0) {
            if (atom_add_acqrel(&g_gb[bh][sub * 32]) == 7u) {
                atomicExch(&g_gb[bh][sub * 32], 0u);
                if (atom_add_acqrel(&g_gr[bh * 32]) == 7u) {
                    atomicExch(&g_gr[bh * 32], 0u);
                    st_release(&g_gg[bh * 32], genv);
                }
            }
            unsigned v;
            do { v = ld_acquire(&g_gg[bh * 32]); } while ((int)(v - genv) < 0);
        }
        __syncthreads();
    }
}

// ---------------------------------------------------------------------------
// Output head.
// ---------------------------------------------------------------------------
__global__ __launch_bounds__(256) void out_proj(
    const float* __restrict__ H2, const float* __restrict__ Wout,
    const float* __restrict__ bout, float* __restrict__ out)
{
    int w = (blockIdx.x * blockDim.x + threadIdx.x) >> 5;
    int lane = threadIdx.x & 31;
    if (w >= TT * BB) return;
    const float4* h  = (const float4*)(H2 + (size_t)w * HH);
    const float4* wv = (const float4*)Wout;
    float acc = 0.0f;
    #pragma unroll
    for (int i = lane; i < 128; i += 32) {
        float4 a = __ldg(h + i);
        float4 bb = __ldg(wv + i);
        acc += a.x*bb.x + a.y*bb.y + a.z*bb.z + a.w*bb.w;
    }
    #pragma unroll
    for (int off = 16; off; off >>= 1) acc += __shfl_xor_sync(0xffffffffu, acc, off);
    if (lane == 0) out[w] = 1.0f / (1.0f + expf(-(acc + __ldg(bout))));
}

// ---------------------------------------------------------------------------
extern "C" void kernel_launch(void* const* d_in, const int* in_sizes, int n_in,
                              void* d_out, int out_size)
{
    const float* x     = (const float*)d_in[0];
    const float* Wih1  = (const float*)d_in[1];
    const float* Whh1  = (const float*)d_in[2];
    const float* bih1  = (const float*)d_in[3];
    const float* bhh1  = (const float*)d_in[4];
    const float* Wih2  = (const float*)d_in[5];
    const float* Whh2  = (const float*)d_in[6];
    const float* bih2  = (const float*)d_in[7];
    const float* bhh2  = (const float*)d_in[8];
    const float* Wout  = (const float*)d_in[9];
    const float* bout  = (const float*)d_in[10];
    float* out = (float*)d_out;

    void *xg_p, *h1_p, *h2_p;
    cudaGetSymbolAddress(&xg_p, g_xg);
    cudaGetSymbolAddress(&h1_p, g_h1);
    cudaGetSymbolAddress(&h2_p, g_h2);
    float* xg = (float*)xg_p;
    float* h1 = (float*)h1_p;
    float* h2 = (float*)h2_p;

    cudaFuncSetAttribute(lstm_rec, cudaFuncAttributeMaxDynamicSharedMemorySize, REC_SMEM);
    cudaFuncSetAttribute(gemm_mma, cudaFuncAttributeMaxDynamicSharedMemorySize, GSMEM);

    dim3 ggrid(16, 1024);   // (N/128, M/128)

    // Layer 1
    prep_a<<<(TT * BB * 256 + 255) / 256, 256>>>(x, TT * BB * 256);
    prep_wih<<<(2048 * 256) / 256, 256>>>(Wih1, 256);
    gemm_mma<<<ggrid, 256, GSMEM>>>(bih1, bhh1, xg, 256);
    prep_w<<<2048, 256>>>(Whh1);
    lstm_rec<<<NCTA, 256, REC_SMEM>>>(xg, h1, 0);   // writes g_ah/g_al (layer-2 A)
    // Layer 2 (xg reused)
    prep_wih<<<(2048 * 512) / 256, 256>>>(Wih2, 512);
    gemm_mma<<<ggrid, 256, GSMEM>>>(bih2, bhh2, xg, 512);
    prep_w<<<2048, 256>>>(Whh2);
    lstm_rec<<<NCTA, 256, REC_SMEM>>>(xg, h2, 1);   // writes f32 H for head
    // Head
    out_proj<<<(TT * BB * 32 + 255) / 256, 256>>>(h2, Wout, bout, out);
}

// round 11
// speedup vs baseline: 3.3402x; 1.2053x over previous
#include <cuda_runtime.h>
#include <cuda_bf16.h>
#include <math.h>
#include <stdint.h>

#define TT 2048
#define BB 64
#define HH 512
#define GG 2048

typedef unsigned long long u64;

// Scratch (module-load allocated).
__device__ float g_xg[268435456];                    // [T][B][4H] f32 (reused per layer)
__device__ float g_h2[67108864];                     // layer-2 H (head input)
__device__ __align__(16) __nv_bfloat16 g_ah[67108864];  // A image hi (x-split / h1-split)
__device__ __align__(16) __nv_bfloat16 g_al[67108864];  // A image lo
__device__ __align__(16) __nv_bfloat16 g_wih_h[1048576]; // W_ih hi [2048][512]
__device__ __align__(16) __nv_bfloat16 g_wih_l[1048576];
__device__ __align__(16) __nv_bfloat16 g_wb[2][64][32][512];      // [split][jgrp][row][k]
__device__ __align__(16) __nv_bfloat16 g_hb[2][3][2][32][512];    // [split][par3][bh][b][j]
__device__ unsigned g_qf[8 * 32];                    // [bh*4+quartile] flags, 128B apart

__device__ __forceinline__ float sigm_f(float x) {
    return __fdividef(1.0f, 1.0f + __expf(-x));
}
__device__ __forceinline__ float tanh_f(float x) {
    float ax = fabsf(x);
    float e = __expf(-2.0f * ax);
    float r = __fdividef(1.0f - e, 1.0f + e);
    return copysignf(r, x);
}
__device__ __forceinline__ uint32_t smem_u32(const void* p) {
    uint32_t a;
    asm("{ .reg .u64 t; cvta.to.shared.u64 t, %1; cvt.u32.u64 %0, t; }" : "=r"(a) : "l"(p));
    return a;
}
__device__ __forceinline__ void atom_add_release(unsigned* p) {
    unsigned o;
    asm volatile("atom.acq_rel.gpu.global.add.u32 %0, [%1], %2;"
                 : "=r"(o) : "l"(p), "r"(1u) : "memory");
}
__device__ __forceinline__ unsigned ld_acquire(unsigned* p) {
    unsigned v;
    asm volatile("ld.acquire.gpu.global.u32 %0, [%1];" : "=r"(v) : "l"(p) : "memory");
    return v;
}

#define LDSM_X4(r0, r1, r2, r3, addr) \
    asm volatile("ldmatrix.sync.aligned.m8n8.x4.shared.b16 {%0,%1,%2,%3}, [%4];" \
        : "=r"(r0), "=r"(r1), "=r"(r2), "=r"(r3) : "r"(addr))
#define LDSM_X2(r0, r1, addr) \
    asm volatile("ldmatrix.sync.aligned.m8n8.x2.shared.b16 {%0,%1}, [%2];" \
        : "=r"(r0), "=r"(r1) : "r"(addr))
#define MMA_BF16(d0, d1, d2, d3, a0, a1, a2, a3, b0, b1) \
    asm volatile("mma.sync.aligned.m16n8k16.row.col.f32.bf16.bf16.f32 " \
        "{%0,%1,%2,%3}, {%4,%5,%6,%7}, {%8,%9}, {%0,%1,%2,%3};" \
        : "+f"(d0), "+f"(d1), "+f"(d2), "+f"(d3) \
        : "r"(a0), "r"(a1), "r"(a2), "r"(a3), "r"(b0), "r"(b1))
#define CP16(dst, src) \
    asm volatile("cp.async.cg.shared.global [%0], [%1], 16;" :: "r"(dst), "l"(src))

// ---------------------------------------------------------------------------
// prep_a: split f32 array into bf16 hi/lo images; ALSO resets the flag array
// (block 0) so every graph replay starts from a clean sync state.
// ---------------------------------------------------------------------------
__global__ __launch_bounds__(256) void prep_a(const float* __restrict__ src, int total)
{
    if (blockIdx.x == 0 && threadIdx.x < 8) g_qf[threadIdx.x * 32] = 0;
    int idx = blockIdx.x * 256 + threadIdx.x;
    if (idx >= total) return;
    float v = src[idx];
    __nv_bfloat16 h = __float2bfloat16(v);
    g_ah[idx] = h;
    g_al[idx] = __float2bfloat16(v - __bfloat162float(h));
}

// ---------------------------------------------------------------------------
// prep_wih: split W_ih [2048][K] f32 into bf16 hi/lo at fixed pitch 512.
// ---------------------------------------------------------------------------
__global__ __launch_bounds__(256) void prep_wih(const float* __restrict__ W, int K)
{
    int idx = blockIdx.x * 256 + threadIdx.x;
    int n = idx / K;
    int k = idx - n * K;
    float v = W[idx];
    __nv_bfloat16 h = __float2bfloat16(v);
    g_wih_h[n * 512 + k] = h;
    g_wih_l[n * 512 + k] = __float2bfloat16(v - __bfloat162float(h));
}

// ---------------------------------------------------------------------------
// gemm_mma: C[M x 2048] = A[M x K]*W[2048 x K]^T + bi + bh (3-split bf16 mma).
// CTA tile 128x128, 8 warps (64x32), K-chunk 32, cp.async 2-stage. (R9)
// ---------------------------------------------------------------------------
#define KC 32
#define APB 80
#define REG (128 * APB)
#define STG (4 * REG)
#define GSMEM (2 * STG)

__global__ __launch_bounds__(256) void gemm_mma(
    const float* __restrict__ bi, const float* __restrict__ bh,
    float* __restrict__ C, int K)
{
    extern __shared__ __align__(16) char gsm[];
    const uint32_t smb = smem_u32(gsm);
    const int tid = threadIdx.x;
    const int wid = tid >> 5, lane = tid & 31;
    const int n0 = blockIdx.x * 128;
    const int m0 = blockIdx.y * 128;
    const int wm = (wid & 1) * 64;
    const int wn = (wid >> 1) * 32;

    auto load_chunk = [&](int c, int s) {
        int kb = c * KC;
        uint32_t base = smb + s * STG;
        #pragma unroll
        for (int j = 0; j < 8; j++) {
            int u = tid + j * 256;
            int r = u >> 9;
            int e = u & 511;
            int row = e >> 2, q = e & 3;
            const __nv_bfloat16* src;
            if (r == 0)      src = g_ah + (size_t)(m0 + row) * K + kb + q * 8;
            else if (r == 1) src = g_al + (size_t)(m0 + row) * K + kb + q * 8;
            else if (r == 2) src = g_wih_h + (size_t)(n0 + row) * 512 + kb + q * 8;
            else             src = g_wih_l + (size_t)(n0 + row) * 512 + kb + q * 8;
            CP16(base + r * REG + row * APB + q * 16, src);
        }
        asm volatile("cp.async.commit_group;");
    };

    float acc[4][4][4];
    #pragma unroll
    for (int a = 0; a < 4; a++)
        #pragma unroll
        for (int b = 0; b < 4; b++)
            #pragma unroll
            for (int cix = 0; cix < 4; cix++) acc[a][b][cix] = 0.0f;

    const int NC = K / KC;
    load_chunk(0, 0);
    for (int c = 0; c < NC; c++) {
        if (c + 1 < NC) {
            load_chunk(c + 1, (c + 1) & 1);
            asm volatile("cp.async.wait_group 1;");
        } else {
            asm volatile("cp.async.wait_group 0;");
        }
        __syncthreads();
        uint32_t st = smb + (c & 1) * STG;
        #pragma unroll
        for (int ks = 0; ks < 2; ks++) {
            uint32_t ko = ks * 32;
            uint32_t Ah[4][4], Al[4][4], Bh[4][2], Bl[4][2];
            #pragma unroll
            for (int f = 0; f < 4; f++) {
                uint32_t ar = st + (uint32_t)(wm + f * 16 + (lane & 15)) * APB
                            + ((lane >> 4) * 16) + ko;
                LDSM_X4(Ah[f][0], Ah[f][1], Ah[f][2], Ah[f][3], ar);
                LDSM_X4(Al[f][0], Al[f][1], Al[f][2], Al[f][3], ar + REG);
                uint32_t br = st + 2 * REG + (uint32_t)(wn + f * 8 + (lane & 7)) * APB
                            + (((lane >> 3) & 1) * 16) + ko;
                LDSM_X2(Bh[f][0], Bh[f][1], br);
                LDSM_X2(Bl[f][0], Bl[f][1], br + REG);
            }
            #pragma unroll
            for (int mf = 0; mf < 4; mf++)
                #pragma unroll
                for (int nf = 0; nf < 4; nf++) {
                    MMA_BF16(acc[mf][nf][0], acc[mf][nf][1], acc[mf][nf][2], acc[mf][nf][3],
                             Ah[mf][0], Ah[mf][1], Ah[mf][2], Ah[mf][3], Bh[nf][0], Bh[nf][1]);
                    MMA_BF16(acc[mf][nf][0], acc[mf][nf][1], acc[mf][nf][2], acc[mf][nf][3],
                             Ah[mf][0], Ah[mf][1], Ah[mf][2], Ah[mf][3], Bl[nf][0], Bl[nf][1]);
                    MMA_BF16(acc[mf][nf][0], acc[mf][nf][1], acc[mf][nf][2], acc[mf][nf][3],
                             Al[mf][0], Al[mf][1], Al[mf][2], Al[mf][3], Bh[nf][0], Bh[nf][1]);
                }
        }
        __syncthreads();
    }

    #pragma unroll
    for (int nf = 0; nf < 4; nf++) {
        int n = n0 + wn + nf * 8 + (lane & 3) * 2;
        float b0 = __ldg(&bi[n]) + __ldg(&bh[n]);
        float b1 = __ldg(&bi[n + 1]) + __ldg(&bh[n + 1]);
        #pragma unroll
        for (int mf = 0; mf < 4; mf++) {
            int m = m0 + wm + mf * 16 + (lane >> 2);
            *(float2*)&C[(size_t)m * GG + n] =
                make_float2(acc[mf][nf][0] + b0, acc[mf][nf][1] + b1);
            *(float2*)&C[(size_t)(m + 8) * GG + n] =
                make_float2(acc[mf][nf][2] + b0, acc[mf][nf][3] + b1);
        }
    }
}

// ---------------------------------------------------------------------------
// prep_w: split Whh into bf16 hi/lo with gate-interleaved row ordering.
// ---------------------------------------------------------------------------
__global__ __launch_bounds__(256) void prep_w(const float* __restrict__ Whh)
{
    int idx  = blockIdx.x * 256 + threadIdx.x;
    int jgrp = idx >> 13;
    int r    = (idx >> 8) & 31;
    int k    = (idx & 255) * 2;
    int wrow = (r & 3) * 512 + jgrp * 8 + (r >> 2);

    float v0 = __ldg(&Whh[(size_t)wrow * HH + k]);
    float v1 = __ldg(&Whh[(size_t)wrow * HH + k + 1]);
    __nv_bfloat16 h0 = __float2bfloat16(v0);
    __nv_bfloat16 h1 = __float2bfloat16(v1);
    g_wb[0][jgrp][r][k]     = h0;
    g_wb[0][jgrp][r][k + 1] = h1;
    g_wb[1][jgrp][r][k]     = __float2bfloat16(v0 - __bfloat162float(h0));
    g_wb[1][jgrp][r][k + 1] = __float2bfloat16(v1 - __bfloat162float(h1));
}

// ---------------------------------------------------------------------------
// Persistent warp-MMA recurrence, NO global barrier: per-quartile producer
// flags (release-atom after h stores; acquire-poll before staging) + triple-
// buffered h images make each step a pipelined dataflow handoff.
// 128 CTAs: jgrp(64) x bh(2), 256 threads.
// ---------------------------------------------------------------------------
#define NCTA 128
#define PITCH 520
#define WBLK (32 * PITCH * 2)
#define OFF_W 0
#define OFF_H (2 * WBLK)
#define OFF_D (4 * WBLK)
#define REC_SMEM (OFF_D + 32 * 33 * 4)

__global__ __launch_bounds__(256, 1) void lstm_rec(
    const float* __restrict__ xg, float* __restrict__ H, int isL2, unsigned qbase)
{
    extern __shared__ char smc[];
    const uint32_t smb = smem_u32(smc);
    float* sD = (float*)(smc + OFF_D);

    const int tid  = threadIdx.x;
    const int wid  = tid >> 5;
    const int lane = tid & 31;
    const int jgrp = blockIdx.x >> 1;
    const int bh   = blockIdx.x & 1;
    const int j0   = jgrp * 8;
    unsigned* myflag = &g_qf[(bh * 4 + (jgrp >> 4)) * 32];

    // Resident W tiles (hi + lo), padded rows.
    {
        uint4* dst = (uint4*)smc;
        #pragma unroll 2
        for (int s = 0; s < 2; s++) {
            const uint4* src = (const uint4*)&g_wb[s][jgrp][0][0];
            uint4* d = dst + s * (WBLK / 16);
            for (int i = tid; i < 2048; i += 256) {
                int row = i >> 6, c = i & 63;
                d[row * 65 + c] = __ldg(src + i);
            }
        }
    }

    const int arow = lane & 15;
    const uint32_t akoff = (lane >> 4) * 16;
    const int brow = lane & 7;
    const uint32_t bkoff = ((lane >> 3) & 1) * 16;
    const int m0 = (wid & 1) * 16;
    const int n0 = (wid >> 1) * 8;

    const uint32_t aHi0 = smb + OFF_W + (uint32_t)(m0 + arow) * (PITCH * 2) + akoff;
    const uint32_t aLo0 = aHi0 + WBLK;
    const uint32_t bHi0 = smb + OFF_H + (uint32_t)(n0 + brow) * (PITCH * 2) + bkoff;
    const uint32_t bLo0 = bHi0 + WBLK;

    const int u  = tid & 7;
    const int b  = tid >> 3;
    const int gb = bh * 32 + b;
    float c = 0.0f;

    for (int t = 0; t < TT; t++) {
        // xg prefetch first (DRAM latency overlapped with flag poll).
        float xv0 = __ldg(&xg[((size_t)t * BB + gb) * GG +        j0 + u]);
        float xv1 = __ldg(&xg[((size_t)t * BB + gb) * GG +  512 + j0 + u]);
        float xv2 = __ldg(&xg[((size_t)t * BB + gb) * GG + 1024 + j0 + u]);
        float xv3 = __ldg(&xg[((size_t)t * BB + gb) * GG + 1536 + j0 + u]);

        if (t > 0) {
            // Wait for all 4 quartiles of h(t-1) (4 threads poll in parallel).
            if (tid < 4) {
                unsigned target = qbase + 16u * (unsigned)t;
                unsigned* fp = &g_qf[(bh * 4 + tid) * 32];
                unsigned v;
                do { v = ld_acquire(fp); } while ((int)(v - target) < 0);
            }
            __syncthreads();

            // Stage h(t-1) as 4 cp.async chunk groups.
            int par = (t - 1) % 3;
            const __nv_bfloat16* baseH = &g_hb[0][par][bh][0][0];
            const __nv_bfloat16* baseL = &g_hb[1][par][bh][0][0];
            #pragma unroll
            for (int ck = 0; ck < 4; ck++) {
                #pragma unroll
                for (int j = 0; j < 2; j++) {
                    int i = tid * 2 + j;          // 0..511
                    int row = i >> 4, q = i & 15;
                    uint32_t dst = smb + OFF_H + (uint32_t)row * (PITCH * 2)
                                 + (uint32_t)(ck * 16 + q) * 16;
                    CP16(dst, baseH + row * 512 + ck * 128 + q * 8);
                    CP16(dst + WBLK, baseL + row * 512 + ck * 128 + q * 8);
                }
                asm volatile("cp.async.commit_group;");
            }

            // MMA, chunk-pipelined.
            float d0 = 0.f, d1 = 0.f, d2 = 0.f, d3 = 0.f;
            #pragma unroll
            for (int ck = 0; ck < 4; ck++) {
                if (ck == 0)      asm volatile("cp.async.wait_group 3;");
                else if (ck == 1) asm volatile("cp.async.wait_group 2;");
                else if (ck == 2) asm volatile("cp.async.wait_group 1;");
                else              asm volatile("cp.async.wait_group 0;");
                __syncthreads();
                #pragma unroll
                for (int ks = 0; ks < 8; ks++) {
                    uint32_t ko = (uint32_t)(ck * 8 + ks) * 32;
                    uint32_t ah0, ah1, ah2, ah3, al0, al1, al2, al3;
                    uint32_t bhr0, bhr1, blr0, blr1;
                    LDSM_X4(ah0, ah1, ah2, ah3, aHi0 + ko);
                    LDSM_X4(al0, al1, al2, al3, aLo0 + ko);
                    LDSM_X2(bhr0, bhr1, bHi0 + ko);
                    LDSM_X2(blr0, blr1, bLo0 + ko);
                    MMA_BF16(d0, d1, d2, d3, ah0, ah1, ah2, ah3, bhr0, bhr1);
                    MMA_BF16(d0, d1, d2, d3, ah0, ah1, ah2, ah3, blr0, blr1);
                    MMA_BF16(d0, d1, d2, d3, al0, al1, al2, al3, bhr0, bhr1);
                }
            }
            {
                int gid = lane >> 2, tig = lane & 3;
                int row = m0 + gid, col = n0 + tig * 2;
                sD[row * 33 + col]           = d0;
                sD[row * 33 + col + 1]       = d1;
                sD[(row + 8) * 33 + col]     = d2;
                sD[(row + 8) * 33 + col + 1] = d3;
            }
            __syncthreads();
        }

        // Fused pointwise: gates of unit u, batch b (tile row = u*4+g).
        {
            float p0 = xv0, p1 = xv1, p2 = xv2, p3 = xv3;
            if (t > 0) {
                p0 += sD[(u * 4 + 0) * 33 + b];
                p1 += sD[(u * 4 + 1) * 33 + b];
                p2 += sD[(u * 4 + 2) * 33 + b];
                p3 += sD[(u * 4 + 3) * 33 + b];
            }
            float gi = sigm_f(p0);
            float gf = sigm_f(p1);
            float gz = tanh_f(p2);
            float go = sigm_f(p3);
            c = gf * c + gi * gz;
            float hv = go * tanh_f(c);

            __nv_bfloat16 hi = __float2bfloat16(hv);
            __nv_bfloat16 lo = __float2bfloat16(hv - __bfloat162float(hi));
            int par = t % 3;
            g_hb[0][par][bh][b][j0 + u] = hi;
            g_hb[1][par][bh][b][j0 + u] = lo;
            if (isL2) {
                H[((size_t)t * BB + gb) * HH + j0 + u] = hv;   // out_proj input
            } else {
                size_t aidx = ((size_t)t * BB + gb) * HH + j0 + u;
                g_ah[aidx] = hi;                               // layer-2 GEMM A image
                g_al[aidx] = lo;
            }
        }

        // Publish: this CTA's 8 units of h(t) are visible (release-cumulative
        // after __syncthreads).
        __syncthreads();
        if (tid == 0) atom_add_release(myflag);
    }
}

// ---------------------------------------------------------------------------
// Output head.
// ---------------------------------------------------------------------------
__global__ __launch_bounds__(256) void out_proj(
    const float* __restrict__ H2, const float* __restrict__ Wout,
    const float* __restrict__ bout, float* __restrict__ out)
{
    int w = (blockIdx.x * blockDim.x + threadIdx.x) >> 5;
    int lane = threadIdx.x & 31;
    if (w >= TT * BB) return;
    const float4* h  = (const float4*)(H2 + (size_t)w * HH);
    const float4* wv = (const float4*)Wout;
    float acc = 0.0f;
    #pragma unroll
    for (int i = lane; i < 128; i += 32) {
        float4 a = __ldg(h + i);
        float4 bb = __ldg(wv + i);
        acc += a.x*bb.x + a.y*bb.y + a.z*bb.z + a.w*bb.w;
    }
    #pragma unroll
    for (int off = 16; off; off >>= 1) acc += __shfl_xor_sync(0xffffffffu, acc, off);
    if (lane == 0) out[w] = 1.0f / (1.0f + expf(-(acc + __ldg(bout))));
}

// ---------------------------------------------------------------------------
extern "C" void kernel_launch(void* const* d_in, const int* in_sizes, int n_in,
                              void* d_out, int out_size)
{
    const float* x     = (const float*)d_in[0];
    const float* Wih1  = (const float*)d_in[1];
    const float* Whh1  = (const float*)d_in[2];
    const float* bih1  = (const float*)d_in[3];
    const float* bhh1  = (const float*)d_in[4];
    const float* Wih2  = (const float*)d_in[5];
    const float* Whh2  = (const float*)d_in[6];
    const float* bih2  = (const float*)d_in[7];
    const float* bhh2  = (const float*)d_in[8];
    const float* Wout  = (const float*)d_in[9];
    const float* bout  = (const float*)d_in[10];
    float* out = (float*)d_out;

    void *xg_p, *h2_p;
    cudaGetSymbolAddress(&xg_p, g_xg);
    cudaGetSymbolAddress(&h2_p, g_h2);
    float* xg = (float*)xg_p;
    float* h2 = (float*)h2_p;

    cudaFuncSetAttribute(lstm_rec, cudaFuncAttributeMaxDynamicSharedMemorySize, REC_SMEM);
    cudaFuncSetAttribute(gemm_mma, cudaFuncAttributeMaxDynamicSharedMemorySize, GSMEM);

    dim3 ggrid(16, 1024);   // (N/128, M/128)

    // Layer 1
    prep_a<<<(TT * BB * 256 + 255) / 256, 256>>>(x, TT * BB * 256);  // also resets g_qf
    prep_wih<<<(2048 * 256) / 256, 256>>>(Wih1, 256);
    gemm_mma<<<ggrid, 256, GSMEM>>>(bih1, bhh1, xg, 256);
    prep_w<<<2048, 256>>>(Whh1);
    lstm_rec<<<NCTA, 256, REC_SMEM>>>(xg, h2, 0, 0u);        // writes g_ah/g_al
    // Layer 2 (xg reused); flags continue from 16*TT per quartile
    prep_wih<<<(2048 * 512) / 256, 256>>>(Wih2, 512);
    gemm_mma<<<ggrid, 256, GSMEM>>>(bih2, bhh2, xg, 512);
    prep_w<<<2048, 256>>>(Whh2);
    lstm_rec<<<NCTA, 256, REC_SMEM>>>(xg, h2, 1, 16u * TT);  // writes f32 H
    // Head
    out_proj<<<(TT * BB * 32 + 255) / 256, 256>>>(h2, Wout, bout, out);
}